// round 10
// baseline (speedup 1.0000x reference)
#include <cuda_runtime.h>
#include <cuda_bf16.h>
#include <math.h>
#include <stdint.h>

// Problem constants
#define B_    4
#define S_    2048
#define HID_  1536
#define H_    12
#define HKV_  2
#define D_    128
#define NGROUPS_ 6
#define NSLOTS_ 16384
#define NTOK  (B_ * S_)            // 8192
#define QKV_N (H_*D_ + 2*HKV_*D_)  // 2048

// Scratch (device globals; allocation in kernel_launch is forbidden)
__device__ float g_qkv[(size_t)NTOK * QKV_N];   // 64 MB
__device__ __nv_bfloat16 g_xhi [(size_t)NTOK * HID_];
__device__ __nv_bfloat16 g_xlo [(size_t)NTOK * HID_];
__device__ __nv_bfloat16 g_wqhi[(size_t)QKV_N * HID_];
__device__ __nv_bfloat16 g_wqlo[(size_t)QKV_N * HID_];
__device__ __nv_bfloat16 g_wohi[(size_t)HID_ * HID_];
__device__ __nv_bfloat16 g_wolo[(size_t)HID_ * HID_];
__device__ __nv_bfloat16 g_aohi[(size_t)NTOK * HID_];
__device__ __nv_bfloat16 g_aolo[(size_t)NTOK * HID_];
// Attention operand buffers (hi/lo splits)
__device__ __nv_bfloat16 g_qhi[(size_t)B_ * H_ * S_ * D_];
__device__ __nv_bfloat16 g_qlo[(size_t)B_ * H_ * S_ * D_];
__device__ __nv_bfloat16 g_khi[(size_t)B_ * HKV_ * S_ * D_];
__device__ __nv_bfloat16 g_klo[(size_t)B_ * HKV_ * S_ * D_];
__device__ __nv_bfloat16 g_vhi[(size_t)B_ * HKV_ * D_ * S_];  // transposed [d][s]
__device__ __nv_bfloat16 g_vlo[(size_t)B_ * HKV_ * D_ * S_];

// ---------------------------------------------------------------------------
// Portable PTX helpers
// ---------------------------------------------------------------------------
__device__ __forceinline__ uint32_t s2u(const void* p) {
    uint32_t a;
    asm("{ .reg .u64 t; cvta.to.shared.u64 t, %1; cvt.u32.u64 %0, t; }"
        : "=r"(a) : "l"(p));
    return a;
}

#define CP_ASYNC16(dst, src) \
    asm volatile("cp.async.cg.shared.global [%0], [%1], 16;" \
                 :: "r"(dst), "l"(src))
#define CP_COMMIT() asm volatile("cp.async.commit_group;")
#define CP_WAIT1()  asm volatile("cp.async.wait_group 1;")
#define CP_WAIT0()  asm volatile("cp.async.wait_group 0;")

#define LDSM4(r0, r1, r2, r3, addr) \
    asm volatile("ldmatrix.sync.aligned.m8n8.x4.shared.b16 {%0,%1,%2,%3}, [%4];" \
                 : "=r"(r0), "=r"(r1), "=r"(r2), "=r"(r3) : "r"(addr))

#define MMA16816(d, a, b) \
    asm volatile("mma.sync.aligned.m16n8k16.row.col.f32.bf16.bf16.f32 " \
                 "{%0,%1,%2,%3}, {%4,%5,%6,%7}, {%8,%9}, {%0,%1,%2,%3};" \
                 : "+f"((d)[0]), "+f"((d)[1]), "+f"((d)[2]), "+f"((d)[3]) \
                 : "r"((a)[0]), "r"((a)[1]), "r"((a)[2]), "r"((a)[3]), \
                   "r"((b)[0]), "r"((b)[1]))

__device__ __forceinline__ float ex2f(float x) {
    float r;
    asm("ex2.approx.ftz.f32 %0, %1;" : "=f"(r) : "f"(x));
    return r;
}

__device__ __forceinline__ uint32_t packbf(float a, float b) {
    __nv_bfloat162 t = __floats2bfloat162_rn(a, b);
    return *(uint32_t*)&t;
}

// gemm smem swizzle (64B rows, 4x 16B chunks)
__device__ __forceinline__ uint32_t swz(int r, int c) {
    return (uint32_t)(r * 64 + ((c ^ ((r >> 1) & 3)) << 4));
}
// 256B rows, 16x 16B chunks
__device__ __forceinline__ uint32_t swzq(int r, int c) {
    return (uint32_t)(r * 256 + ((c ^ (r & 7)) << 4));
}
// 128B rows, 8x 16B chunks
__device__ __forceinline__ uint32_t swzv(int r, int c) {
    return (uint32_t)(r * 128 + ((c ^ (r & 7)) << 4));
}

__device__ __forceinline__ void split1(float x, __nv_bfloat16& h, __nv_bfloat16& l) {
    h = __float2bfloat16(x);
    l = __float2bfloat16(x - __bfloat162float(h));
}

__device__ __forceinline__ uint32_t pack2(__nv_bfloat16 a, __nv_bfloat16 b) {
    return (uint32_t)__bfloat16_as_ushort(a) | ((uint32_t)__bfloat16_as_ushort(b) << 16);
}

__device__ __forceinline__ void split4(float4 v, uint2* hi, uint2* lo) {
    __nv_bfloat16 h0, h1, h2, h3, l0, l1, l2, l3;
    split1(v.x, h0, l0); split1(v.y, h1, l1);
    split1(v.z, h2, l2); split1(v.w, h3, l3);
    uint2 hv, lv;
    hv.x = pack2(h0, h1); hv.y = pack2(h2, h3);
    lv.x = pack2(l0, l1); lv.y = pack2(l2, l3);
    *hi = hv; *lo = lv;
}

// ---------------------------------------------------------------------------
// Merged preprocessing: splits of x/Wqkv/Wo + cache copies, one kernel.
// ---------------------------------------------------------------------------
#define P_N0 (NTOK * HID_ / 4)                       // x
#define P_N1 (P_N0 + QKV_N * HID_ / 4)               // + Wqkv
#define P_N2 (P_N1 + HID_ * HID_ / 4)                // + Wo
#define P_N3 (P_N2 + NSLOTS_ * HKV_ * D_ / 4)        // + caches

__global__ void prep(const float4* __restrict__ x, const float4* __restrict__ wq,
                     const float4* __restrict__ wo,
                     const float4* __restrict__ kci, const float4* __restrict__ vci,
                     uint2* __restrict__ xhi, uint2* __restrict__ xlo,
                     uint2* __restrict__ wqhi, uint2* __restrict__ wqlo,
                     uint2* __restrict__ wohi, uint2* __restrict__ wolo,
                     float4* __restrict__ kc, float4* __restrict__ vc)
{
    int i = blockIdx.x * blockDim.x + threadIdx.x;
    if (i < P_N0) {
        split4(x[i], xhi + i, xlo + i);
    } else if (i < P_N1) {
        int j = i - P_N0;
        split4(wq[j], wqhi + j, wqlo + j);
    } else if (i < P_N2) {
        int j = i - P_N1;
        split4(wo[j], wohi + j, wolo + j);
    } else if (i < P_N3) {
        int j = i - P_N2;
        kc[j] = kci[j];
        vc[j] = vci[j];
    }
}

// ---------------------------------------------------------------------------
// mma.sync GEMM, 256x128 CTA tile, 64x64 warp tile, 3-stage cp.async pipeline.
// C = Ahi*Bhi^T + Ahi*Blo^T + Alo*Bhi^T (+bias)
// Stage layout: Ahi 16KB | Alo 16KB | Bhi 8KB | Blo 8KB  (48KB)
// ---------------------------------------------------------------------------
#define G2_ATILE  16384
#define G2_BTILE  8192
#define G2_STAGE  49152
#define MT_SMEM   (3 * G2_STAGE)   // 144 KB

__device__ __forceinline__ void g2_stage_load(
    const __nv_bfloat16* __restrict__ Ahi, const __nv_bfloat16* __restrict__ Alo,
    const __nv_bfloat16* __restrict__ Bhi, const __nv_bfloat16* __restrict__ Blo,
    int m0, int n0, int K, int k0, uint32_t st, int tid)
{
    // A: 256 rows x 4 chunks, hi+lo = 2048 items; B: 128 rows x 4 chunks x2 = 1024
    #pragma unroll
    for (int it = 0; it < 4; it++) {
        int idx = tid + it * 256;              // 0..1023
        int r = idx >> 2, c = idx & 3;         // A row 0..255
        const char* sh = (const char*)(Ahi + (size_t)(m0 + r) * K + k0) + c * 16;
        const char* sl = (const char*)(Alo + (size_t)(m0 + r) * K + k0) + c * 16;
        CP_ASYNC16(st + swz(r, c),            sh);
        CP_ASYNC16(st + G2_ATILE + swz(r, c), sl);
    }
    #pragma unroll
    for (int it = 0; it < 2; it++) {
        int idx = tid + it * 256;              // 0..511
        int r = idx >> 2, c = idx & 3;         // B row 0..127
        const char* sh = (const char*)(Bhi + (size_t)(n0 + r) * K + k0) + c * 16;
        const char* sl = (const char*)(Blo + (size_t)(n0 + r) * K + k0) + c * 16;
        CP_ASYNC16(st + 2 * G2_ATILE + swz(r, c),            sh);
        CP_ASYNC16(st + 2 * G2_ATILE + G2_BTILE + swz(r, c), sl);
    }
}

__global__ __launch_bounds__(256, 1)
void gemm_mma(const __nv_bfloat16* __restrict__ Ahi, const __nv_bfloat16* __restrict__ Alo,
              const __nv_bfloat16* __restrict__ Bhi, const __nv_bfloat16* __restrict__ Blo,
              const float* __restrict__ bias, float* __restrict__ C,
              int M, int N, int K)
{
    extern __shared__ char smg[];
    uint32_t sb = s2u(smg);
    int tid = threadIdx.x;
    int wid = tid >> 5, lane = tid & 31;
    int wm = wid & 3, wn = wid >> 2;         // 4 x 2 warp grid
    int mbase = wm * 64, nbase = wn * 64;
    int m0 = blockIdx.y * 256, n0 = blockIdx.x * 128;

    float acc[4][8][4];
    #pragma unroll
    for (int i = 0; i < 4; i++)
        #pragma unroll
        for (int j = 0; j < 8; j++)
            #pragma unroll
            for (int q = 0; q < 4; q++) acc[i][j][q] = 0.f;

    const int nkt = K >> 5;

    g2_stage_load(Ahi, Alo, Bhi, Blo, m0, n0, K, 0, sb, tid);
    CP_COMMIT();
    g2_stage_load(Ahi, Alo, Bhi, Blo, m0, n0, K, 32, sb + G2_STAGE, tid);
    CP_COMMIT();

    int lrow = lane & 15;
    int lsel = lane >> 4;

    for (int kt = 0; kt < nkt; kt++) {
        if (kt == nkt - 1) { CP_WAIT0(); } else { CP_WAIT1(); }
        __syncthreads();
        if (kt + 2 < nkt) {
            g2_stage_load(Ahi, Alo, Bhi, Blo, m0, n0, K, (kt + 2) << 5,
                          sb + (uint32_t)((kt + 2) % 3) * G2_STAGE, tid);
            CP_COMMIT();
        }
        uint32_t sbuf = sb + (uint32_t)(kt % 3) * G2_STAGE;

        #pragma unroll
        for (int ks = 0; ks < 2; ks++) {
            int kc = ks * 2;
            uint32_t ah[4][4], al[4][4], bh[8][2], bl[8][2];
            #pragma unroll
            for (int f = 0; f < 4; f++) {
                int r = mbase + f * 16 + lrow;
                int c = kc + lsel;
                LDSM4(ah[f][0], ah[f][1], ah[f][2], ah[f][3], sbuf + swz(r, c));
                LDSM4(al[f][0], al[f][1], al[f][2], al[f][3],
                      sbuf + G2_ATILE + swz(r, c));
            }
            #pragma unroll
            for (int g = 0; g < 4; g++) {
                int r = nbase + g * 16 + lrow;
                int c = kc + lsel;
                uint32_t r0, r1, r2, r3;
                LDSM4(r0, r1, r2, r3, sbuf + 2 * G2_ATILE + swz(r, c));
                bh[2*g][0] = r0; bh[2*g][1] = r2;
                bh[2*g+1][0] = r1; bh[2*g+1][1] = r3;
                LDSM4(r0, r1, r2, r3, sbuf + 2 * G2_ATILE + G2_BTILE + swz(r, c));
                bl[2*g][0] = r0; bl[2*g][1] = r2;
                bl[2*g+1][0] = r1; bl[2*g+1][1] = r3;
            }
            #pragma unroll
            for (int mi = 0; mi < 4; mi++)
                #pragma unroll
                for (int nj = 0; nj < 8; nj++) {
                    MMA16816(acc[mi][nj], ah[mi], bh[nj]);
                    MMA16816(acc[mi][nj], ah[mi], bl[nj]);
                    MMA16816(acc[mi][nj], al[mi], bh[nj]);
                }
        }
    }

    int erow = lane >> 2;
    int ecol = (lane & 3) * 2;
    #pragma unroll
    for (int mi = 0; mi < 4; mi++) {
        #pragma unroll
        for (int nj = 0; nj < 8; nj++) {
            int col = n0 + nbase + nj * 8 + ecol;
            float b0 = bias ? bias[col]     : 0.f;
            float b1 = bias ? bias[col + 1] : 0.f;
            int r0 = m0 + mbase + mi * 16 + erow;
            float2 v0 = make_float2(acc[mi][nj][0] + b0, acc[mi][nj][1] + b1);
            float2 v1 = make_float2(acc[mi][nj][2] + b0, acc[mi][nj][3] + b1);
            *(float2*)(C + (size_t)r0 * N + col)       = v0;
            *(float2*)(C + (size_t)(r0 + 8) * N + col) = v1;
        }
    }
}

// ---------------------------------------------------------------------------
// Fused Q RoPE + scale + hi/lo split -> [b][h][s][d]. qkv untouched.
// ---------------------------------------------------------------------------
__global__ void qrope(const float* __restrict__ qkv, const float* __restrict__ cosp,
                      const float* __restrict__ sinp,
                      __nv_bfloat16* __restrict__ qhi, __nv_bfloat16* __restrict__ qlo)
{
    int idx = blockIdx.x * blockDim.x + threadIdx.x;
    if (idx >= NTOK * H_ * 16) return;
    int t  = idx / (H_ * 16);
    int r  = idx - t * (H_ * 16);
    int h  = r >> 4, d4 = r & 15;
    int d  = d4 * 4;
    int b  = t >> 11, s = t & 2047;

    const float* rowp = qkv + (size_t)t * QKV_N + h * D_;
    float4 x1 = *(const float4*)(rowp + d);
    float4 x2 = *(const float4*)(rowp + d + 64);
    const float* cp = cosp + (size_t)t * D_;
    const float* sp = sinp + (size_t)t * D_;
    float4 c1 = *(const float4*)(cp + d),      s1 = *(const float4*)(sp + d);
    float4 c2 = *(const float4*)(cp + d + 64), s2 = *(const float4*)(sp + d + 64);

    const float qs = 0.08838834764831845f * 1.4426950408889634f;
    float o1[4], o2[4];
    o1[0] = (x1.x * c1.x - x2.x * s1.x) * qs;
    o1[1] = (x1.y * c1.y - x2.y * s1.y) * qs;
    o1[2] = (x1.z * c1.z - x2.z * s1.z) * qs;
    o1[3] = (x1.w * c1.w - x2.w * s1.w) * qs;
    o2[0] = (x2.x * c2.x + x1.x * s2.x) * qs;
    o2[1] = (x2.y * c2.y + x1.y * s2.y) * qs;
    o2[2] = (x2.z * c2.z + x1.z * s2.z) * qs;
    o2[3] = (x2.w * c2.w + x1.w * s2.w) * qs;

    __nv_bfloat16 hh[4], ll[4];
    uint2 hv, lv;
    size_t o = ((size_t)(b * H_ + h) * S_ + s) * D_;
    #pragma unroll
    for (int j = 0; j < 4; j++) split1(o1[j], hh[j], ll[j]);
    hv.x = pack2(hh[0], hh[1]); hv.y = pack2(hh[2], hh[3]);
    lv.x = pack2(ll[0], ll[1]); lv.y = pack2(ll[2], ll[3]);
    *(uint2*)(qhi + o + d) = hv;
    *(uint2*)(qlo + o + d) = lv;
    #pragma unroll
    for (int j = 0; j < 4; j++) split1(o2[j], hh[j], ll[j]);
    hv.x = pack2(hh[0], hh[1]); hv.y = pack2(hh[2], hh[3]);
    lv.x = pack2(ll[0], ll[1]); lv.y = pack2(ll[2], ll[3]);
    *(uint2*)(qhi + o + d + 64) = hv;
    *(uint2*)(qlo + o + d + 64) = lv;
}

// ---------------------------------------------------------------------------
// Fused KV: K rope + split + cache scatter; V split + transpose + cache scatter.
// ---------------------------------------------------------------------------
__global__ __launch_bounds__(256)
void kvrope(const float* __restrict__ qkv, const float* __restrict__ cosp,
            const float* __restrict__ sinp, const int* __restrict__ slot_mapping,
            float* __restrict__ kc, float* __restrict__ vc,
            __nv_bfloat16* __restrict__ khi, __nv_bfloat16* __restrict__ klo,
            __nv_bfloat16* __restrict__ vhi, __nv_bfloat16* __restrict__ vlo)
{
    __shared__ float vbuf[64][132];
    int blk = blockIdx.x;
    int st64 = blk & 31;
    int kvh  = (blk >> 5) & 1;
    int b    = blk >> 6;
    int s0 = st64 * 64;
    int tid = threadIdx.x;

    #pragma unroll
    for (int it = 0; it < 4; it++) {
        int idx = tid + it * 256;
        int r = idx >> 4, d4 = idx & 15;
        int d = d4 * 4;
        int t = b * S_ + s0 + r;
        const float* rowp = qkv + (size_t)t * QKV_N + H_*D_ + kvh * D_;
        float4 x1 = *(const float4*)(rowp + d);
        float4 x2 = *(const float4*)(rowp + d + 64);
        const float* cp = cosp + (size_t)t * D_;
        const float* sp = sinp + (size_t)t * D_;
        float4 c1 = *(const float4*)(cp + d),      s1 = *(const float4*)(sp + d);
        float4 c2 = *(const float4*)(cp + d + 64), s2 = *(const float4*)(sp + d + 64);
        float4 o1, o2;
        o1.x = x1.x * c1.x - x2.x * s1.x;
        o1.y = x1.y * c1.y - x2.y * s1.y;
        o1.z = x1.z * c1.z - x2.z * s1.z;
        o1.w = x1.w * c1.w - x2.w * s1.w;
        o2.x = x2.x * c2.x + x1.x * s2.x;
        o2.y = x2.y * c2.y + x1.y * s2.y;
        o2.z = x2.z * c2.z + x1.z * s2.z;
        o2.w = x2.w * c2.w + x1.w * s2.w;

        int slot = slot_mapping[t];
        float* kcp = kc + (size_t)slot * (HKV_*D_) + kvh * D_;
        *(float4*)(kcp + d)      = o1;
        *(float4*)(kcp + d + 64) = o2;

        __nv_bfloat16 hh[4], ll[4];
        uint2 hv, lv;
        size_t ko = ((size_t)(b * HKV_ + kvh) * S_ + s0 + r) * D_;
        split1(o1.x, hh[0], ll[0]); split1(o1.y, hh[1], ll[1]);
        split1(o1.z, hh[2], ll[2]); split1(o1.w, hh[3], ll[3]);
        hv.x = pack2(hh[0], hh[1]); hv.y = pack2(hh[2], hh[3]);
        lv.x = pack2(ll[0], ll[1]); lv.y = pack2(ll[2], ll[3]);
        *(uint2*)(khi + ko + d) = hv;
        *(uint2*)(klo + ko + d) = lv;
        split1(o2.x, hh[0], ll[0]); split1(o2.y, hh[1], ll[1]);
        split1(o2.z, hh[2], ll[2]); split1(o2.w, hh[3], ll[3]);
        hv.x = pack2(hh[0], hh[1]); hv.y = pack2(hh[2], hh[3]);
        lv.x = pack2(ll[0], ll[1]); lv.y = pack2(ll[2], ll[3]);
        *(uint2*)(khi + ko + d + 64) = hv;
        *(uint2*)(klo + ko + d + 64) = lv;
    }

    #pragma unroll
    for (int it = 0; it < 8; it++) {
        int idx = tid + it * 256;
        int r = idx >> 5, c4 = idx & 31;
        int t = b * S_ + s0 + r;
        float4 vv = *(const float4*)(qkv + (size_t)t * QKV_N
                                     + H_*D_ + HKV_*D_ + kvh * D_ + c4 * 4);
        int slot = slot_mapping[t];
        *(float4*)(vc + (size_t)slot * (HKV_*D_) + kvh * D_ + c4 * 4) = vv;
        vbuf[r][c4*4+0] = vv.x; vbuf[r][c4*4+1] = vv.y;
        vbuf[r][c4*4+2] = vv.z; vbuf[r][c4*4+3] = vv.w;
    }
    __syncthreads();

    int d = tid >> 1, half = tid & 1;
    uint32_t hw[16], lw[16];
    #pragma unroll
    for (int j = 0; j < 16; j++) {
        float x0 = vbuf[half*32 + 2*j    ][d];
        float x1 = vbuf[half*32 + 2*j + 1][d];
        __nv_bfloat16 ha, hb, la, lb;
        split1(x0, ha, la); split1(x1, hb, lb);
        hw[j] = pack2(ha, hb);
        lw[j] = pack2(la, lb);
    }
    size_t o = ((size_t)(b * HKV_ + kvh) * D_ + d) * S_ + s0 + half * 32;
    #pragma unroll
    for (int q = 0; q < 4; q++) {
        *(uint4*)(vhi + o + q * 8) = *(uint4*)&hw[q * 4];
        *(uint4*)(vlo + o + q * 8) = *(uint4*)&lw[q * 4];
    }
}

// ---------------------------------------------------------------------------
// Tensor-core flash attention. BLOCK_M=128 (8 warps x m16), BLOCK_N=64, D=128.
// Writes hi/lo bf16 splits of the output directly.
// ---------------------------------------------------------------------------
#define A2_QBYTES 65536
#define A2_STAGE  65536
#define A2_SMEM   (A2_QBYTES + 2 * A2_STAGE)  // 196608

__global__ __launch_bounds__(256, 1)
void attn2(const __nv_bfloat16* __restrict__ qhi, const __nv_bfloat16* __restrict__ qlo,
           const __nv_bfloat16* __restrict__ khi, const __nv_bfloat16* __restrict__ klo,
           const __nv_bfloat16* __restrict__ vhi, const __nv_bfloat16* __restrict__ vlo,
           __nv_bfloat16* __restrict__ aohi, __nv_bfloat16* __restrict__ aolo)
{
    extern __shared__ char sm2[];
    uint32_t sb = s2u(sm2);
    // heavy-first: largest qt scheduled earliest
    int qt = (int)gridDim.x - 1 - (int)blockIdx.x;
    int h = blockIdx.y, b = blockIdx.z;
    int kvh = h / NGROUPS_;
    int q0 = qt * 128;
    int tid = threadIdx.x, wid = tid >> 5, lane = tid & 31;
    int lrow = lane & 15, lsel = lane >> 4;

    const char* qh_base = (const char*)(qhi + ((size_t)(b * H_ + h) * S_ + q0) * D_);
    const char* ql_base = (const char*)(qlo + ((size_t)(b * H_ + h) * S_ + q0) * D_);
    const char* kh_base = (const char*)(khi + ((size_t)(b * HKV_ + kvh) * S_) * D_);
    const char* kl_base = (const char*)(klo + ((size_t)(b * HKV_ + kvh) * S_) * D_);
    const char* vh_base = (const char*)(vhi + ((size_t)(b * HKV_ + kvh) * D_) * S_);
    const char* vl_base = (const char*)(vlo + ((size_t)(b * HKV_ + kvh) * D_) * S_);

    #pragma unroll
    for (int it = 0; it < 8; it++) {
        int idx = tid + it * 256;
        int r = idx >> 4, c = idx & 15;
        CP_ASYNC16(sb + swzq(r, c),          qh_base + r * 256 + c * 16);
        CP_ASYNC16(sb + 32768 + swzq(r, c),  ql_base + r * 256 + c * 16);
    }

    const int nt = 2 * qt + 2;

    auto load_kv = [&](int t, int st_i) {
        uint32_t st = sb + A2_QBYTES + (uint32_t)st_i * A2_STAGE;
        int k0 = t * 64;
        #pragma unroll
        for (int it = 0; it < 4; it++) {
            int idx = tid + it * 256;
            int r = idx >> 4, c = idx & 15;
            CP_ASYNC16(st + swzq(r, c),          kh_base + (size_t)(k0 + r) * 256 + c * 16);
            CP_ASYNC16(st + 16384 + swzq(r, c),  kl_base + (size_t)(k0 + r) * 256 + c * 16);
        }
        #pragma unroll
        for (int it = 0; it < 4; it++) {
            int idx = tid + it * 256;
            int r = idx >> 3, c = idx & 7;
            CP_ASYNC16(st + 32768 + swzv(r, c),
                       vh_base + (size_t)r * (S_ * 2) + k0 * 2 + c * 16);
            CP_ASYNC16(st + 49152 + swzv(r, c),
                       vl_base + (size_t)r * (S_ * 2) + k0 * 2 + c * 16);
        }
    };

    load_kv(0, 0);
    CP_COMMIT();

    float oacc[16][4];
    #pragma unroll
    for (int i = 0; i < 16; i++)
        #pragma unroll
        for (int j = 0; j < 4; j++) oacc[i][j] = 0.f;
    float m0 = -1e30f, m1 = -1e30f, l0 = 0.f, l1 = 0.f;

    for (int t = 0; t < nt; t++) {
        uint32_t st = sb + A2_QBYTES + (uint32_t)(t & 1) * A2_STAGE;
        if (t + 1 < nt) {
            load_kv(t + 1, (t + 1) & 1);
            CP_COMMIT();
            CP_WAIT1();
        } else {
            CP_WAIT0();
        }
        __syncthreads();

        float sacc[8][4];
        #pragma unroll
        for (int i = 0; i < 8; i++)
            #pragma unroll
            for (int j = 0; j < 4; j++) sacc[i][j] = 0.f;

        #pragma unroll
        for (int kc = 0; kc < 8; kc++) {
            uint32_t qa[4], qla[4];
            LDSM4(qa[0], qa[1], qa[2], qa[3],
                  sb + swzq(wid * 16 + lrow, kc * 2 + lsel));
            LDSM4(qla[0], qla[1], qla[2], qla[3],
                  sb + 32768 + swzq(wid * 16 + lrow, kc * 2 + lsel));
            uint32_t bh[8][2], bl[8][2];
            #pragma unroll
            for (int g = 0; g < 4; g++) {
                uint32_t r0, r1, r2, r3;
                LDSM4(r0, r1, r2, r3, st + swzq(g * 16 + lrow, kc * 2 + lsel));
                bh[2*g][0] = r0; bh[2*g][1] = r2;
                bh[2*g+1][0] = r1; bh[2*g+1][1] = r3;
                LDSM4(r0, r1, r2, r3, st + 16384 + swzq(g * 16 + lrow, kc * 2 + lsel));
                bl[2*g][0] = r0; bl[2*g][1] = r2;
                bl[2*g+1][0] = r1; bl[2*g+1][1] = r3;
            }
            #pragma unroll
            for (int nj = 0; nj < 8; nj++) {
                MMA16816(sacc[nj], qa, bh[nj]);
                MMA16816(sacc[nj], qa, bl[nj]);
                MMA16816(sacc[nj], qla, bh[nj]);
            }
        }

        int k0 = t * 64;
        if (t >= nt - 2) {
            int qr0 = q0 + wid * 16 + (lane >> 2);
            int qr1 = qr0 + 8;
            #pragma unroll
            for (int nj = 0; nj < 8; nj++) {
                int kcol = k0 + nj * 8 + (lane & 3) * 2;
                if (kcol     > qr0) sacc[nj][0] = -1e30f;
                if (kcol + 1 > qr0) sacc[nj][1] = -1e30f;
                if (kcol     > qr1) sacc[nj][2] = -1e30f;
                if (kcol + 1 > qr1) sacc[nj][3] = -1e30f;
            }
        }

        float mx0 = -1e30f, mx1 = -1e30f;
        #pragma unroll
        for (int nj = 0; nj < 8; nj++) {
            mx0 = fmaxf(mx0, fmaxf(sacc[nj][0], sacc[nj][1]));
            mx1 = fmaxf(mx1, fmaxf(sacc[nj][2], sacc[nj][3]));
        }
        mx0 = fmaxf(mx0, __shfl_xor_sync(0xffffffffu, mx0, 1));
        mx0 = fmaxf(mx0, __shfl_xor_sync(0xffffffffu, mx0, 2));
        mx1 = fmaxf(mx1, __shfl_xor_sync(0xffffffffu, mx1, 1));
        mx1 = fmaxf(mx1, __shfl_xor_sync(0xffffffffu, mx1, 2));
        float nm0 = fmaxf(m0, mx0), nm1 = fmaxf(m1, mx1);
        float f0 = ex2f(m0 - nm0), f1 = ex2f(m1 - nm1);
        m0 = nm0; m1 = nm1;

        uint32_t ph[4][4], pl[4][4];
        float rs0 = 0.f, rs1 = 0.f;
        #pragma unroll
        for (int j = 0; j < 4; j++) {
            float pe0 = ex2f(sacc[2*j][0] - nm0);
            float pe1 = ex2f(sacc[2*j][1] - nm0);
            float pe2 = ex2f(sacc[2*j][2] - nm1);
            float pe3 = ex2f(sacc[2*j][3] - nm1);
            float po0 = ex2f(sacc[2*j+1][0] - nm0);
            float po1 = ex2f(sacc[2*j+1][1] - nm0);
            float po2 = ex2f(sacc[2*j+1][2] - nm1);
            float po3 = ex2f(sacc[2*j+1][3] - nm1);
            rs0 += pe0 + pe1 + po0 + po1;
            rs1 += pe2 + pe3 + po2 + po3;
            ph[j][0] = packbf(pe0, pe1);
            ph[j][1] = packbf(pe2, pe3);
            ph[j][2] = packbf(po0, po1);
            ph[j][3] = packbf(po2, po3);
            __nv_bfloat16 hh; float r, q0r;
            hh = __float2bfloat16(pe0); q0r = pe0 - __bfloat162float(hh);
            hh = __float2bfloat16(pe1); r = pe1 - __bfloat162float(hh);
            pl[j][0] = packbf(q0r, r);
            hh = __float2bfloat16(pe2); q0r = pe2 - __bfloat162float(hh);
            hh = __float2bfloat16(pe3); r = pe3 - __bfloat162float(hh);
            pl[j][1] = packbf(q0r, r);
            hh = __float2bfloat16(po0); q0r = po0 - __bfloat162float(hh);
            hh = __float2bfloat16(po1); r = po1 - __bfloat162float(hh);
            pl[j][2] = packbf(q0r, r);
            hh = __float2bfloat16(po2); q0r = po2 - __bfloat162float(hh);
            hh = __float2bfloat16(po3); r = po3 - __bfloat162float(hh);
            pl[j][3] = packbf(q0r, r);
        }
        rs0 += __shfl_xor_sync(0xffffffffu, rs0, 1);
        rs0 += __shfl_xor_sync(0xffffffffu, rs0, 2);
        rs1 += __shfl_xor_sync(0xffffffffu, rs1, 1);
        rs1 += __shfl_xor_sync(0xffffffffu, rs1, 2);
        l0 = l0 * f0 + rs0;
        l1 = l1 * f1 + rs1;
        #pragma unroll
        for (int nj = 0; nj < 16; nj++) {
            oacc[nj][0] *= f0; oacc[nj][1] *= f0;
            oacc[nj][2] *= f1; oacc[nj][3] *= f1;
        }

        #pragma unroll
        for (int j = 0; j < 4; j++) {
            #pragma unroll
            for (int g = 0; g < 8; g++) {
                uint32_t r0, r1, r2, r3, s0r, s1r, s2r, s3r;
                LDSM4(r0, r1, r2, r3, st + 32768 + swzv(g * 16 + lrow, j * 2 + lsel));
                LDSM4(s0r, s1r, s2r, s3r, st + 49152 + swzv(g * 16 + lrow, j * 2 + lsel));
                uint32_t vh0[2] = {r0, r2}, vh1[2] = {r1, r3};
                uint32_t vl0[2] = {s0r, s2r}, vl1[2] = {s1r, s3r};
                MMA16816(oacc[2*g],   ph[j], vh0);
                MMA16816(oacc[2*g],   ph[j], vl0);
                MMA16816(oacc[2*g],   pl[j], vh0);
                MMA16816(oacc[2*g+1], ph[j], vh1);
                MMA16816(oacc[2*g+1], ph[j], vl1);
                MMA16816(oacc[2*g+1], pl[j], vh1);
            }
        }
        __syncthreads();
    }

    float inv0 = 1.f / l0, inv1 = 1.f / l1;
    int r0g = q0 + wid * 16 + (lane >> 2);
    #pragma unroll
    for (int nj = 0; nj < 16; nj++) {
        int d = nj * 8 + (lane & 3) * 2;
        float a0 = oacc[nj][0] * inv0, a1 = oacc[nj][1] * inv0;
        float b0 = oacc[nj][2] * inv1, b1 = oacc[nj][3] * inv1;
        __nv_bfloat16 h0, h1, l0b, l1b;
        split1(a0, h0, l0b); split1(a1, h1, l1b);
        size_t off0 = ((size_t)(b * S_ + r0g)) * HID_ + h * D_ + d;
        *(uint32_t*)(aohi + off0) = pack2(h0, h1);
        *(uint32_t*)(aolo + off0) = pack2(l0b, l1b);
        split1(b0, h0, l0b); split1(b1, h1, l1b);
        size_t off1 = ((size_t)(b * S_ + r0g + 8)) * HID_ + h * D_ + d;
        *(uint32_t*)(aohi + off1) = pack2(h0, h1);
        *(uint32_t*)(aolo + off1) = pack2(l0b, l1b);
    }
}

// ---------------------------------------------------------------------------
extern "C" void kernel_launch(void* const* d_in, const int* in_sizes, int n_in,
                              void* d_out, int out_size)
{
    const float* x     = (const float*)d_in[0];
    const float* cosp  = (const float*)d_in[1];
    const float* sinp  = (const float*)d_in[2];
    const float* kci   = (const float*)d_in[3];
    const float* vci   = (const float*)d_in[4];
    const int*   slot  = (const int*)  d_in[5];
    const float* Wqkv  = (const float*)d_in[6];
    const float* bqkv  = (const float*)d_in[7];
    const float* Wo    = (const float*)d_in[8];

    float* out = (float*)d_out;
    float* kc  = out + (size_t)NTOK * HID_;
    float* vc  = kc  + (size_t)NSLOTS_ * HKV_ * D_;

    float* qkv; cudaGetSymbolAddress((void**)&qkv, g_qkv);
    __nv_bfloat16 *xhi, *xlo, *wqhi, *wqlo, *wohi, *wolo, *aohi, *aolo;
    __nv_bfloat16 *qhi, *qlo, *khi, *klo, *vhi, *vlo;
    cudaGetSymbolAddress((void**)&xhi,  g_xhi);
    cudaGetSymbolAddress((void**)&xlo,  g_xlo);
    cudaGetSymbolAddress((void**)&wqhi, g_wqhi);
    cudaGetSymbolAddress((void**)&wqlo, g_wqlo);
    cudaGetSymbolAddress((void**)&wohi, g_wohi);
    cudaGetSymbolAddress((void**)&wolo, g_wolo);
    cudaGetSymbolAddress((void**)&aohi, g_aohi);
    cudaGetSymbolAddress((void**)&aolo, g_aolo);
    cudaGetSymbolAddress((void**)&qhi,  g_qhi);
    cudaGetSymbolAddress((void**)&qlo,  g_qlo);
    cudaGetSymbolAddress((void**)&khi,  g_khi);
    cudaGetSymbolAddress((void**)&klo,  g_klo);
    cudaGetSymbolAddress((void**)&vhi,  g_vhi);
    cudaGetSymbolAddress((void**)&vlo,  g_vlo);

    cudaFuncSetAttribute(gemm_mma, cudaFuncAttributeMaxDynamicSharedMemorySize, MT_SMEM);
    cudaFuncSetAttribute(attn2, cudaFuncAttributeMaxDynamicSharedMemorySize, A2_SMEM);

    // 0) merged preprocessing: splits + cache copies
    prep<<<(P_N3 + 255) / 256, 256>>>((const float4*)x, (const float4*)Wqkv,
                                      (const float4*)Wo, (const float4*)kci,
                                      (const float4*)vci,
                                      (uint2*)xhi, (uint2*)xlo,
                                      (uint2*)wqhi, (uint2*)wqlo,
                                      (uint2*)wohi, (uint2*)wolo,
                                      (float4*)kc, (float4*)vc);

    // 1) QKV projection (tensor cores, 256x128 tiles)
    gemm_mma<<<dim3(QKV_N / 128, NTOK / 256), 256, MT_SMEM>>>(
        xhi, xlo, wqhi, wqlo, bqkv, qkv, NTOK, QKV_N, HID_);

    // 2) Fused RoPE + split + scatter
    {
        int n = NTOK * H_ * 16;
        qrope<<<(n + 255) / 256, 256>>>(qkv, cosp, sinp, qhi, qlo);
        kvrope<<<B_ * HKV_ * (S_ / 64), 256>>>(qkv, cosp, sinp, slot,
                                               kc, vc, khi, klo, vhi, vlo);
    }

    // 3) Tensor-core flash attention (heavy CTAs first)
    attn2<<<dim3(S_ / 128, H_, B_), 256, A2_SMEM>>>(qhi, qlo, khi, klo, vhi, vlo,
                                                    aohi, aolo);

    // 4) Output projection (tensor cores)
    gemm_mma<<<dim3(HID_ / 128, NTOK / 256), 256, MT_SMEM>>>(
        aohi, aolo, wohi, wolo, nullptr, out, NTOK, HID_, HID_);
}

// round 11
// speedup vs baseline: 1.0827x; 1.0827x over previous
#include <cuda_runtime.h>
#include <cuda_bf16.h>
#include <math.h>
#include <stdint.h>

// Problem constants
#define B_    4
#define S_    2048
#define HID_  1536
#define H_    12
#define HKV_  2
#define D_    128
#define NGROUPS_ 6
#define NSLOTS_ 16384
#define NTOK  (B_ * S_)            // 8192
#define QKV_N (H_*D_ + 2*HKV_*D_)  // 2048

// Scratch (device globals; allocation in kernel_launch is forbidden)
__device__ float g_qkv[(size_t)NTOK * QKV_N];   // 64 MB
__device__ __nv_bfloat16 g_xhi [(size_t)NTOK * HID_];
__device__ __nv_bfloat16 g_xlo [(size_t)NTOK * HID_];
__device__ __nv_bfloat16 g_wqhi[(size_t)QKV_N * HID_];
__device__ __nv_bfloat16 g_wqlo[(size_t)QKV_N * HID_];
__device__ __nv_bfloat16 g_wohi[(size_t)HID_ * HID_];
__device__ __nv_bfloat16 g_wolo[(size_t)HID_ * HID_];
__device__ __nv_bfloat16 g_aohi[(size_t)NTOK * HID_];
__device__ __nv_bfloat16 g_aolo[(size_t)NTOK * HID_];
// Attention operand buffers (hi/lo splits)
__device__ __nv_bfloat16 g_qhi[(size_t)B_ * H_ * S_ * D_];
__device__ __nv_bfloat16 g_qlo[(size_t)B_ * H_ * S_ * D_];
__device__ __nv_bfloat16 g_khi[(size_t)B_ * HKV_ * S_ * D_];
__device__ __nv_bfloat16 g_klo[(size_t)B_ * HKV_ * S_ * D_];
__device__ __nv_bfloat16 g_vhi[(size_t)B_ * HKV_ * D_ * S_];  // transposed [d][s]
__device__ __nv_bfloat16 g_vlo[(size_t)B_ * HKV_ * D_ * S_];

// ---------------------------------------------------------------------------
// Portable PTX helpers
// ---------------------------------------------------------------------------
__device__ __forceinline__ uint32_t s2u(const void* p) {
    uint32_t a;
    asm("{ .reg .u64 t; cvta.to.shared.u64 t, %1; cvt.u32.u64 %0, t; }"
        : "=r"(a) : "l"(p));
    return a;
}

#define CP_ASYNC16(dst, src) \
    asm volatile("cp.async.cg.shared.global [%0], [%1], 16;" \
                 :: "r"(dst), "l"(src))
#define CP_COMMIT() asm volatile("cp.async.commit_group;")
#define CP_WAIT1()  asm volatile("cp.async.wait_group 1;")
#define CP_WAIT0()  asm volatile("cp.async.wait_group 0;")

#define LDSM4(r0, r1, r2, r3, addr) \
    asm volatile("ldmatrix.sync.aligned.m8n8.x4.shared.b16 {%0,%1,%2,%3}, [%4];" \
                 : "=r"(r0), "=r"(r1), "=r"(r2), "=r"(r3) : "r"(addr))

#define MMA16816(d, a, b) \
    asm volatile("mma.sync.aligned.m16n8k16.row.col.f32.bf16.bf16.f32 " \
                 "{%0,%1,%2,%3}, {%4,%5,%6,%7}, {%8,%9}, {%0,%1,%2,%3};" \
                 : "+f"((d)[0]), "+f"((d)[1]), "+f"((d)[2]), "+f"((d)[3]) \
                 : "r"((a)[0]), "r"((a)[1]), "r"((a)[2]), "r"((a)[3]), \
                   "r"((b)[0]), "r"((b)[1]))

__device__ __forceinline__ float ex2f(float x) {
    float r;
    asm("ex2.approx.ftz.f32 %0, %1;" : "=f"(r) : "f"(x));
    return r;
}

__device__ __forceinline__ uint32_t packbf(float a, float b) {
    __nv_bfloat162 t = __floats2bfloat162_rn(a, b);
    return *(uint32_t*)&t;
}

// gemm smem swizzle (64B rows, 4x 16B chunks)
__device__ __forceinline__ uint32_t swz(int r, int c) {
    return (uint32_t)(r * 64 + ((c ^ ((r >> 1) & 3)) << 4));
}
// 256B rows, 16x 16B chunks
__device__ __forceinline__ uint32_t swzq(int r, int c) {
    return (uint32_t)(r * 256 + ((c ^ (r & 7)) << 4));
}
// 128B rows, 8x 16B chunks
__device__ __forceinline__ uint32_t swzv(int r, int c) {
    return (uint32_t)(r * 128 + ((c ^ (r & 7)) << 4));
}

__device__ __forceinline__ void split1(float x, __nv_bfloat16& h, __nv_bfloat16& l) {
    h = __float2bfloat16(x);
    l = __float2bfloat16(x - __bfloat162float(h));
}

__device__ __forceinline__ uint32_t pack2(__nv_bfloat16 a, __nv_bfloat16 b) {
    return (uint32_t)__bfloat16_as_ushort(a) | ((uint32_t)__bfloat16_as_ushort(b) << 16);
}

__device__ __forceinline__ void split4(float4 v, uint2* hi, uint2* lo) {
    __nv_bfloat16 h0, h1, h2, h3, l0, l1, l2, l3;
    split1(v.x, h0, l0); split1(v.y, h1, l1);
    split1(v.z, h2, l2); split1(v.w, h3, l3);
    uint2 hv, lv;
    hv.x = pack2(h0, h1); hv.y = pack2(h2, h3);
    lv.x = pack2(l0, l1); lv.y = pack2(l2, l3);
    *hi = hv; *lo = lv;
}

// ---------------------------------------------------------------------------
// Merged preprocessing: splits of x/Wqkv/Wo + cache copies, one kernel.
// ---------------------------------------------------------------------------
#define P_N0 (NTOK * HID_ / 4)                       // x
#define P_N1 (P_N0 + QKV_N * HID_ / 4)               // + Wqkv
#define P_N2 (P_N1 + HID_ * HID_ / 4)                // + Wo
#define P_N3 (P_N2 + NSLOTS_ * HKV_ * D_ / 4)        // + caches

__global__ void prep(const float4* __restrict__ x, const float4* __restrict__ wq,
                     const float4* __restrict__ wo,
                     const float4* __restrict__ kci, const float4* __restrict__ vci,
                     uint2* __restrict__ xhi, uint2* __restrict__ xlo,
                     uint2* __restrict__ wqhi, uint2* __restrict__ wqlo,
                     uint2* __restrict__ wohi, uint2* __restrict__ wolo,
                     float4* __restrict__ kc, float4* __restrict__ vc)
{
    int i = blockIdx.x * blockDim.x + threadIdx.x;
    if (i < P_N0) {
        split4(x[i], xhi + i, xlo + i);
    } else if (i < P_N1) {
        int j = i - P_N0;
        split4(wq[j], wqhi + j, wqlo + j);
    } else if (i < P_N2) {
        int j = i - P_N1;
        split4(wo[j], wohi + j, wolo + j);
    } else if (i < P_N3) {
        int j = i - P_N2;
        kc[j] = kci[j];
        vc[j] = vci[j];
    }
}

// ---------------------------------------------------------------------------
// mma.sync GEMM (round-9 config: 128x128 CTA, 32x64 warp tile, 3-stage).
// C = Ahi*Bhi^T + Ahi*Blo^T + Alo*Bhi^T (+bias)
// ---------------------------------------------------------------------------
#define MT_TILE   8192
#define MT_STAGE  32768
#define MT_SMEM   (3 * MT_STAGE)   // 96 KB -> 2 CTAs/SM

__device__ __forceinline__ void mt_stage_load(
    const __nv_bfloat16* __restrict__ Ahi, const __nv_bfloat16* __restrict__ Alo,
    const __nv_bfloat16* __restrict__ Bhi, const __nv_bfloat16* __restrict__ Blo,
    int m0, int n0, int K, int k0, uint32_t sstage, int tid)
{
    #pragma unroll
    for (int it = 0; it < 8; it++) {
        int idx = tid + it * 256;
        int t   = idx >> 9;
        int rem = idx & 511;
        int r   = rem >> 2;
        int c   = rem & 3;
        const __nv_bfloat16* base = (t == 0) ? Ahi : (t == 1) ? Alo
                                  : (t == 2) ? Bhi : Blo;
        int row0 = (t < 2) ? m0 : n0;
        const char* src = (const char*)(base + (size_t)(row0 + r) * K + k0) + c * 16;
        uint32_t dst = sstage + (uint32_t)t * MT_TILE + swz(r, c);
        CP_ASYNC16(dst, src);
    }
}

__global__ __launch_bounds__(256)
void gemm_mma(const __nv_bfloat16* __restrict__ Ahi, const __nv_bfloat16* __restrict__ Alo,
              const __nv_bfloat16* __restrict__ Bhi, const __nv_bfloat16* __restrict__ Blo,
              const float* __restrict__ bias, float* __restrict__ C,
              int M, int N, int K)
{
    extern __shared__ char smg[];
    uint32_t sb = s2u(smg);
    int tid = threadIdx.x;
    int wid = tid >> 5, lane = tid & 31;
    int wm = wid & 3, wn = wid >> 2;
    int mbase = wm * 32, nbase = wn * 64;
    int m0 = blockIdx.y * 128, n0 = blockIdx.x * 128;

    float acc[2][8][4];
    #pragma unroll
    for (int i = 0; i < 2; i++)
        #pragma unroll
        for (int j = 0; j < 8; j++)
            #pragma unroll
            for (int q = 0; q < 4; q++) acc[i][j][q] = 0.f;

    const int nkt = K >> 5;

    mt_stage_load(Ahi, Alo, Bhi, Blo, m0, n0, K, 0, sb, tid);
    CP_COMMIT();
    mt_stage_load(Ahi, Alo, Bhi, Blo, m0, n0, K, 32, sb + MT_STAGE, tid);
    CP_COMMIT();

    int lrow = lane & 15;
    int lsel = lane >> 4;

    for (int kt = 0; kt < nkt; kt++) {
        if (kt == nkt - 1) { CP_WAIT0(); } else { CP_WAIT1(); }
        __syncthreads();
        if (kt + 2 < nkt) {
            mt_stage_load(Ahi, Alo, Bhi, Blo, m0, n0, K, (kt + 2) << 5,
                          sb + (uint32_t)((kt + 2) % 3) * MT_STAGE, tid);
            CP_COMMIT();
        }
        uint32_t sbuf = sb + (uint32_t)(kt % 3) * MT_STAGE;

        #pragma unroll
        for (int ks = 0; ks < 2; ks++) {
            int kc = ks * 2;
            uint32_t ah[2][4], al[2][4], bh[8][2], bl[8][2];
            #pragma unroll
            for (int f = 0; f < 2; f++) {
                int r = mbase + f * 16 + lrow;
                int c = kc + lsel;
                LDSM4(ah[f][0], ah[f][1], ah[f][2], ah[f][3], sbuf + swz(r, c));
                LDSM4(al[f][0], al[f][1], al[f][2], al[f][3],
                      sbuf + MT_TILE + swz(r, c));
            }
            #pragma unroll
            for (int g = 0; g < 4; g++) {
                int r = nbase + g * 16 + lrow;
                int c = kc + lsel;
                uint32_t r0, r1, r2, r3;
                LDSM4(r0, r1, r2, r3, sbuf + 2 * MT_TILE + swz(r, c));
                bh[2*g][0] = r0; bh[2*g][1] = r2;
                bh[2*g+1][0] = r1; bh[2*g+1][1] = r3;
                LDSM4(r0, r1, r2, r3, sbuf + 3 * MT_TILE + swz(r, c));
                bl[2*g][0] = r0; bl[2*g][1] = r2;
                bl[2*g+1][0] = r1; bl[2*g+1][1] = r3;
            }
            #pragma unroll
            for (int mi = 0; mi < 2; mi++)
                #pragma unroll
                for (int nj = 0; nj < 8; nj++) {
                    MMA16816(acc[mi][nj], ah[mi], bh[nj]);
                    MMA16816(acc[mi][nj], ah[mi], bl[nj]);
                    MMA16816(acc[mi][nj], al[mi], bh[nj]);
                }
        }
    }

    int erow = lane >> 2;
    int ecol = (lane & 3) * 2;
    #pragma unroll
    for (int mi = 0; mi < 2; mi++) {
        #pragma unroll
        for (int nj = 0; nj < 8; nj++) {
            int col = n0 + nbase + nj * 8 + ecol;
            float b0 = bias ? bias[col]     : 0.f;
            float b1 = bias ? bias[col + 1] : 0.f;
            int r0 = m0 + mbase + mi * 16 + erow;
            float2 v0 = make_float2(acc[mi][nj][0] + b0, acc[mi][nj][1] + b1);
            float2 v1 = make_float2(acc[mi][nj][2] + b0, acc[mi][nj][3] + b1);
            *(float2*)(C + (size_t)r0 * N + col)       = v0;
            *(float2*)(C + (size_t)(r0 + 8) * N + col) = v1;
        }
    }
}

// ---------------------------------------------------------------------------
// Merged RoPE kernel: blocks [0, QB) do Q rope+split; [QB, QB+KB) do KV work.
// ---------------------------------------------------------------------------
#define ROPE_QB ((NTOK * H_ * 16) / 256)     // 6144 blocks, 256 thr
#define ROPE_KB (B_ * HKV_ * (S_ / 64))      // 256 blocks

__global__ __launch_bounds__(256)
void ropeall(const float* __restrict__ qkv, const float* __restrict__ cosp,
             const float* __restrict__ sinp, const int* __restrict__ slot_mapping,
             float* __restrict__ kc, float* __restrict__ vc,
             __nv_bfloat16* __restrict__ qhi, __nv_bfloat16* __restrict__ qlo,
             __nv_bfloat16* __restrict__ khi, __nv_bfloat16* __restrict__ klo,
             __nv_bfloat16* __restrict__ vhi, __nv_bfloat16* __restrict__ vlo)
{
    __shared__ float vbuf[64][132];
    int tid = threadIdx.x;

    if (blockIdx.x < ROPE_QB) {
        // ---- Q: rope + scale + split -> [b][h][s][d] ----
        int idx = blockIdx.x * 256 + tid;
        int t  = idx / (H_ * 16);
        int r  = idx - t * (H_ * 16);
        int h  = r >> 4, d4 = r & 15;
        int d  = d4 * 4;
        int b  = t >> 11, s = t & 2047;

        const float* rowp = qkv + (size_t)t * QKV_N + h * D_;
        float4 x1 = *(const float4*)(rowp + d);
        float4 x2 = *(const float4*)(rowp + d + 64);
        const float* cp = cosp + (size_t)t * D_;
        const float* sp = sinp + (size_t)t * D_;
        float4 c1 = *(const float4*)(cp + d),      s1 = *(const float4*)(sp + d);
        float4 c2 = *(const float4*)(cp + d + 64), s2 = *(const float4*)(sp + d + 64);

        const float qs = 0.08838834764831845f * 1.4426950408889634f;
        float o1[4], o2[4];
        o1[0] = (x1.x * c1.x - x2.x * s1.x) * qs;
        o1[1] = (x1.y * c1.y - x2.y * s1.y) * qs;
        o1[2] = (x1.z * c1.z - x2.z * s1.z) * qs;
        o1[3] = (x1.w * c1.w - x2.w * s1.w) * qs;
        o2[0] = (x2.x * c2.x + x1.x * s2.x) * qs;
        o2[1] = (x2.y * c2.y + x1.y * s2.y) * qs;
        o2[2] = (x2.z * c2.z + x1.z * s2.z) * qs;
        o2[3] = (x2.w * c2.w + x1.w * s2.w) * qs;

        __nv_bfloat16 hh[4], ll[4];
        uint2 hv, lv;
        size_t o = ((size_t)(b * H_ + h) * S_ + s) * D_;
        #pragma unroll
        for (int j = 0; j < 4; j++) split1(o1[j], hh[j], ll[j]);
        hv.x = pack2(hh[0], hh[1]); hv.y = pack2(hh[2], hh[3]);
        lv.x = pack2(ll[0], ll[1]); lv.y = pack2(ll[2], ll[3]);
        *(uint2*)(qhi + o + d) = hv;
        *(uint2*)(qlo + o + d) = lv;
        #pragma unroll
        for (int j = 0; j < 4; j++) split1(o2[j], hh[j], ll[j]);
        hv.x = pack2(hh[0], hh[1]); hv.y = pack2(hh[2], hh[3]);
        lv.x = pack2(ll[0], ll[1]); lv.y = pack2(ll[2], ll[3]);
        *(uint2*)(qhi + o + d + 64) = hv;
        *(uint2*)(qlo + o + d + 64) = lv;
        return;
    }

    // ---- KV path ----
    int blk = blockIdx.x - ROPE_QB;
    int st64 = blk & 31;
    int kvh  = (blk >> 5) & 1;
    int b    = blk >> 6;
    int s0 = st64 * 64;

    #pragma unroll
    for (int it = 0; it < 4; it++) {
        int idx = tid + it * 256;
        int r = idx >> 4, d4 = idx & 15;
        int d = d4 * 4;
        int t = b * S_ + s0 + r;
        const float* rowp = qkv + (size_t)t * QKV_N + H_*D_ + kvh * D_;
        float4 x1 = *(const float4*)(rowp + d);
        float4 x2 = *(const float4*)(rowp + d + 64);
        const float* cp = cosp + (size_t)t * D_;
        const float* sp = sinp + (size_t)t * D_;
        float4 c1 = *(const float4*)(cp + d),      s1 = *(const float4*)(sp + d);
        float4 c2 = *(const float4*)(cp + d + 64), s2 = *(const float4*)(sp + d + 64);
        float4 o1, o2;
        o1.x = x1.x * c1.x - x2.x * s1.x;
        o1.y = x1.y * c1.y - x2.y * s1.y;
        o1.z = x1.z * c1.z - x2.z * s1.z;
        o1.w = x1.w * c1.w - x2.w * s1.w;
        o2.x = x2.x * c2.x + x1.x * s2.x;
        o2.y = x2.y * c2.y + x1.y * s2.y;
        o2.z = x2.z * c2.z + x1.z * s2.z;
        o2.w = x2.w * c2.w + x1.w * s2.w;

        int slot = slot_mapping[t];
        float* kcp = kc + (size_t)slot * (HKV_*D_) + kvh * D_;
        *(float4*)(kcp + d)      = o1;
        *(float4*)(kcp + d + 64) = o2;

        __nv_bfloat16 hh[4], ll[4];
        uint2 hv, lv;
        size_t ko = ((size_t)(b * HKV_ + kvh) * S_ + s0 + r) * D_;
        split1(o1.x, hh[0], ll[0]); split1(o1.y, hh[1], ll[1]);
        split1(o1.z, hh[2], ll[2]); split1(o1.w, hh[3], ll[3]);
        hv.x = pack2(hh[0], hh[1]); hv.y = pack2(hh[2], hh[3]);
        lv.x = pack2(ll[0], ll[1]); lv.y = pack2(ll[2], ll[3]);
        *(uint2*)(khi + ko + d) = hv;
        *(uint2*)(klo + ko + d) = lv;
        split1(o2.x, hh[0], ll[0]); split1(o2.y, hh[1], ll[1]);
        split1(o2.z, hh[2], ll[2]); split1(o2.w, hh[3], ll[3]);
        hv.x = pack2(hh[0], hh[1]); hv.y = pack2(hh[2], hh[3]);
        lv.x = pack2(ll[0], ll[1]); lv.y = pack2(ll[2], ll[3]);
        *(uint2*)(khi + ko + d + 64) = hv;
        *(uint2*)(klo + ko + d + 64) = lv;
    }

    #pragma unroll
    for (int it = 0; it < 8; it++) {
        int idx = tid + it * 256;
        int r = idx >> 5, c4 = idx & 31;
        int t = b * S_ + s0 + r;
        float4 vv = *(const float4*)(qkv + (size_t)t * QKV_N
                                     + H_*D_ + HKV_*D_ + kvh * D_ + c4 * 4);
        int slot = slot_mapping[t];
        *(float4*)(vc + (size_t)slot * (HKV_*D_) + kvh * D_ + c4 * 4) = vv;
        vbuf[r][c4*4+0] = vv.x; vbuf[r][c4*4+1] = vv.y;
        vbuf[r][c4*4+2] = vv.z; vbuf[r][c4*4+3] = vv.w;
    }
    __syncthreads();

    int d = tid >> 1, half = tid & 1;
    uint32_t hw[16], lw[16];
    #pragma unroll
    for (int j = 0; j < 16; j++) {
        float x0 = vbuf[half*32 + 2*j    ][d];
        float x1 = vbuf[half*32 + 2*j + 1][d];
        __nv_bfloat16 ha, hb, la, lb;
        split1(x0, ha, la); split1(x1, hb, lb);
        hw[j] = pack2(ha, hb);
        lw[j] = pack2(la, lb);
    }
    size_t o = ((size_t)(b * HKV_ + kvh) * D_ + d) * S_ + s0 + half * 32;
    #pragma unroll
    for (int q = 0; q < 4; q++) {
        *(uint4*)(vhi + o + q * 8) = *(uint4*)&hw[q * 4];
        *(uint4*)(vlo + o + q * 8) = *(uint4*)&lw[q * 4];
    }
}

// ---------------------------------------------------------------------------
// Tensor-core flash attention. BLOCK_M=128 (8 warps x m16), BLOCK_N=64, D=128.
// Heavy-first scheduling; writes hi/lo bf16 output splits directly.
// ---------------------------------------------------------------------------
#define A2_QBYTES 65536
#define A2_STAGE  65536
#define A2_SMEM   (A2_QBYTES + 2 * A2_STAGE)  // 196608

__global__ __launch_bounds__(256, 1)
void attn2(const __nv_bfloat16* __restrict__ qhi, const __nv_bfloat16* __restrict__ qlo,
           const __nv_bfloat16* __restrict__ khi, const __nv_bfloat16* __restrict__ klo,
           const __nv_bfloat16* __restrict__ vhi, const __nv_bfloat16* __restrict__ vlo,
           __nv_bfloat16* __restrict__ aohi, __nv_bfloat16* __restrict__ aolo)
{
    extern __shared__ char sm2[];
    uint32_t sb = s2u(sm2);
    int qt = (int)gridDim.x - 1 - (int)blockIdx.x;   // heavy-first
    int h = blockIdx.y, b = blockIdx.z;
    int kvh = h / NGROUPS_;
    int q0 = qt * 128;
    int tid = threadIdx.x, wid = tid >> 5, lane = tid & 31;
    int lrow = lane & 15, lsel = lane >> 4;

    const char* qh_base = (const char*)(qhi + ((size_t)(b * H_ + h) * S_ + q0) * D_);
    const char* ql_base = (const char*)(qlo + ((size_t)(b * H_ + h) * S_ + q0) * D_);
    const char* kh_base = (const char*)(khi + ((size_t)(b * HKV_ + kvh) * S_) * D_);
    const char* kl_base = (const char*)(klo + ((size_t)(b * HKV_ + kvh) * S_) * D_);
    const char* vh_base = (const char*)(vhi + ((size_t)(b * HKV_ + kvh) * D_) * S_);
    const char* vl_base = (const char*)(vlo + ((size_t)(b * HKV_ + kvh) * D_) * S_);

    #pragma unroll
    for (int it = 0; it < 8; it++) {
        int idx = tid + it * 256;
        int r = idx >> 4, c = idx & 15;
        CP_ASYNC16(sb + swzq(r, c),          qh_base + r * 256 + c * 16);
        CP_ASYNC16(sb + 32768 + swzq(r, c),  ql_base + r * 256 + c * 16);
    }

    const int nt = 2 * qt + 2;

    auto load_kv = [&](int t, int st_i) {
        uint32_t st = sb + A2_QBYTES + (uint32_t)st_i * A2_STAGE;
        int k0 = t * 64;
        #pragma unroll
        for (int it = 0; it < 4; it++) {
            int idx = tid + it * 256;
            int r = idx >> 4, c = idx & 15;
            CP_ASYNC16(st + swzq(r, c),          kh_base + (size_t)(k0 + r) * 256 + c * 16);
            CP_ASYNC16(st + 16384 + swzq(r, c),  kl_base + (size_t)(k0 + r) * 256 + c * 16);
        }
        #pragma unroll
        for (int it = 0; it < 4; it++) {
            int idx = tid + it * 256;
            int r = idx >> 3, c = idx & 7;
            CP_ASYNC16(st + 32768 + swzv(r, c),
                       vh_base + (size_t)r * (S_ * 2) + k0 * 2 + c * 16);
            CP_ASYNC16(st + 49152 + swzv(r, c),
                       vl_base + (size_t)r * (S_ * 2) + k0 * 2 + c * 16);
        }
    };

    load_kv(0, 0);
    CP_COMMIT();

    float oacc[16][4];
    #pragma unroll
    for (int i = 0; i < 16; i++)
        #pragma unroll
        for (int j = 0; j < 4; j++) oacc[i][j] = 0.f;
    float m0 = -1e30f, m1 = -1e30f, l0 = 0.f, l1 = 0.f;

    for (int t = 0; t < nt; t++) {
        uint32_t st = sb + A2_QBYTES + (uint32_t)(t & 1) * A2_STAGE;
        if (t + 1 < nt) {
            load_kv(t + 1, (t + 1) & 1);
            CP_COMMIT();
            CP_WAIT1();
        } else {
            CP_WAIT0();
        }
        __syncthreads();

        float sacc[8][4];
        #pragma unroll
        for (int i = 0; i < 8; i++)
            #pragma unroll
            for (int j = 0; j < 4; j++) sacc[i][j] = 0.f;

        #pragma unroll
        for (int kc = 0; kc < 8; kc++) {
            uint32_t qa[4], qla[4];
            LDSM4(qa[0], qa[1], qa[2], qa[3],
                  sb + swzq(wid * 16 + lrow, kc * 2 + lsel));
            LDSM4(qla[0], qla[1], qla[2], qla[3],
                  sb + 32768 + swzq(wid * 16 + lrow, kc * 2 + lsel));
            uint32_t bh[8][2], bl[8][2];
            #pragma unroll
            for (int g = 0; g < 4; g++) {
                uint32_t r0, r1, r2, r3;
                LDSM4(r0, r1, r2, r3, st + swzq(g * 16 + lrow, kc * 2 + lsel));
                bh[2*g][0] = r0; bh[2*g][1] = r2;
                bh[2*g+1][0] = r1; bh[2*g+1][1] = r3;
                LDSM4(r0, r1, r2, r3, st + 16384 + swzq(g * 16 + lrow, kc * 2 + lsel));
                bl[2*g][0] = r0; bl[2*g][1] = r2;
                bl[2*g+1][0] = r1; bl[2*g+1][1] = r3;
            }
            #pragma unroll
            for (int nj = 0; nj < 8; nj++) {
                MMA16816(sacc[nj], qa, bh[nj]);
                MMA16816(sacc[nj], qa, bl[nj]);
                MMA16816(sacc[nj], qla, bh[nj]);
            }
        }

        int k0 = t * 64;
        if (t >= nt - 2) {
            int qr0 = q0 + wid * 16 + (lane >> 2);
            int qr1 = qr0 + 8;
            #pragma unroll
            for (int nj = 0; nj < 8; nj++) {
                int kcol = k0 + nj * 8 + (lane & 3) * 2;
                if (kcol     > qr0) sacc[nj][0] = -1e30f;
                if (kcol + 1 > qr0) sacc[nj][1] = -1e30f;
                if (kcol     > qr1) sacc[nj][2] = -1e30f;
                if (kcol + 1 > qr1) sacc[nj][3] = -1e30f;
            }
        }

        float mx0 = -1e30f, mx1 = -1e30f;
        #pragma unroll
        for (int nj = 0; nj < 8; nj++) {
            mx0 = fmaxf(mx0, fmaxf(sacc[nj][0], sacc[nj][1]));
            mx1 = fmaxf(mx1, fmaxf(sacc[nj][2], sacc[nj][3]));
        }
        mx0 = fmaxf(mx0, __shfl_xor_sync(0xffffffffu, mx0, 1));
        mx0 = fmaxf(mx0, __shfl_xor_sync(0xffffffffu, mx0, 2));
        mx1 = fmaxf(mx1, __shfl_xor_sync(0xffffffffu, mx1, 1));
        mx1 = fmaxf(mx1, __shfl_xor_sync(0xffffffffu, mx1, 2));
        float nm0 = fmaxf(m0, mx0), nm1 = fmaxf(m1, mx1);
        float f0 = ex2f(m0 - nm0), f1 = ex2f(m1 - nm1);
        m0 = nm0; m1 = nm1;

        uint32_t ph[4][4], pl[4][4];
        float rs0 = 0.f, rs1 = 0.f;
        #pragma unroll
        for (int j = 0; j < 4; j++) {
            float pe0 = ex2f(sacc[2*j][0] - nm0);
            float pe1 = ex2f(sacc[2*j][1] - nm0);
            float pe2 = ex2f(sacc[2*j][2] - nm1);
            float pe3 = ex2f(sacc[2*j][3] - nm1);
            float po0 = ex2f(sacc[2*j+1][0] - nm0);
            float po1 = ex2f(sacc[2*j+1][1] - nm0);
            float po2 = ex2f(sacc[2*j+1][2] - nm1);
            float po3 = ex2f(sacc[2*j+1][3] - nm1);
            rs0 += pe0 + pe1 + po0 + po1;
            rs1 += pe2 + pe3 + po2 + po3;
            ph[j][0] = packbf(pe0, pe1);
            ph[j][1] = packbf(pe2, pe3);
            ph[j][2] = packbf(po0, po1);
            ph[j][3] = packbf(po2, po3);
            __nv_bfloat16 hh; float r, q0r;
            hh = __float2bfloat16(pe0); q0r = pe0 - __bfloat162float(hh);
            hh = __float2bfloat16(pe1); r = pe1 - __bfloat162float(hh);
            pl[j][0] = packbf(q0r, r);
            hh = __float2bfloat16(pe2); q0r = pe2 - __bfloat162float(hh);
            hh = __float2bfloat16(pe3); r = pe3 - __bfloat162float(hh);
            pl[j][1] = packbf(q0r, r);
            hh = __float2bfloat16(po0); q0r = po0 - __bfloat162float(hh);
            hh = __float2bfloat16(po1); r = po1 - __bfloat162float(hh);
            pl[j][2] = packbf(q0r, r);
            hh = __float2bfloat16(po2); q0r = po2 - __bfloat162float(hh);
            hh = __float2bfloat16(po3); r = po3 - __bfloat162float(hh);
            pl[j][3] = packbf(q0r, r);
        }
        rs0 += __shfl_xor_sync(0xffffffffu, rs0, 1);
        rs0 += __shfl_xor_sync(0xffffffffu, rs0, 2);
        rs1 += __shfl_xor_sync(0xffffffffu, rs1, 1);
        rs1 += __shfl_xor_sync(0xffffffffu, rs1, 2);
        l0 = l0 * f0 + rs0;
        l1 = l1 * f1 + rs1;
        #pragma unroll
        for (int nj = 0; nj < 16; nj++) {
            oacc[nj][0] *= f0; oacc[nj][1] *= f0;
            oacc[nj][2] *= f1; oacc[nj][3] *= f1;
        }

        #pragma unroll
        for (int j = 0; j < 4; j++) {
            #pragma unroll
            for (int g = 0; g < 8; g++) {
                uint32_t r0, r1, r2, r3, s0r, s1r, s2r, s3r;
                LDSM4(r0, r1, r2, r3, st + 32768 + swzv(g * 16 + lrow, j * 2 + lsel));
                LDSM4(s0r, s1r, s2r, s3r, st + 49152 + swzv(g * 16 + lrow, j * 2 + lsel));
                uint32_t vh0[2] = {r0, r2}, vh1[2] = {r1, r3};
                uint32_t vl0[2] = {s0r, s2r}, vl1[2] = {s1r, s3r};
                MMA16816(oacc[2*g],   ph[j], vh0);
                MMA16816(oacc[2*g],   ph[j], vl0);
                MMA16816(oacc[2*g],   pl[j], vh0);
                MMA16816(oacc[2*g+1], ph[j], vh1);
                MMA16816(oacc[2*g+1], ph[j], vl1);
                MMA16816(oacc[2*g+1], pl[j], vh1);
            }
        }
        __syncthreads();
    }

    float inv0 = 1.f / l0, inv1 = 1.f / l1;
    int r0g = q0 + wid * 16 + (lane >> 2);
    #pragma unroll
    for (int nj = 0; nj < 16; nj++) {
        int d = nj * 8 + (lane & 3) * 2;
        float a0 = oacc[nj][0] * inv0, a1 = oacc[nj][1] * inv0;
        float b0 = oacc[nj][2] * inv1, b1 = oacc[nj][3] * inv1;
        __nv_bfloat16 h0, h1, l0b, l1b;
        split1(a0, h0, l0b); split1(a1, h1, l1b);
        size_t off0 = ((size_t)(b * S_ + r0g)) * HID_ + h * D_ + d;
        *(uint32_t*)(aohi + off0) = pack2(h0, h1);
        *(uint32_t*)(aolo + off0) = pack2(l0b, l1b);
        split1(b0, h0, l0b); split1(b1, h1, l1b);
        size_t off1 = ((size_t)(b * S_ + r0g + 8)) * HID_ + h * D_ + d;
        *(uint32_t*)(aohi + off1) = pack2(h0, h1);
        *(uint32_t*)(aolo + off1) = pack2(l0b, l1b);
    }
}

// ---------------------------------------------------------------------------
extern "C" void kernel_launch(void* const* d_in, const int* in_sizes, int n_in,
                              void* d_out, int out_size)
{
    const float* x     = (const float*)d_in[0];
    const float* cosp  = (const float*)d_in[1];
    const float* sinp  = (const float*)d_in[2];
    const float* kci   = (const float*)d_in[3];
    const float* vci   = (const float*)d_in[4];
    const int*   slot  = (const int*)  d_in[5];
    const float* Wqkv  = (const float*)d_in[6];
    const float* bqkv  = (const float*)d_in[7];
    const float* Wo    = (const float*)d_in[8];

    float* out = (float*)d_out;
    float* kc  = out + (size_t)NTOK * HID_;
    float* vc  = kc  + (size_t)NSLOTS_ * HKV_ * D_;

    float* qkv; cudaGetSymbolAddress((void**)&qkv, g_qkv);
    __nv_bfloat16 *xhi, *xlo, *wqhi, *wqlo, *wohi, *wolo, *aohi, *aolo;
    __nv_bfloat16 *qhi, *qlo, *khi, *klo, *vhi, *vlo;
    cudaGetSymbolAddress((void**)&xhi,  g_xhi);
    cudaGetSymbolAddress((void**)&xlo,  g_xlo);
    cudaGetSymbolAddress((void**)&wqhi, g_wqhi);
    cudaGetSymbolAddress((void**)&wqlo, g_wqlo);
    cudaGetSymbolAddress((void**)&wohi, g_wohi);
    cudaGetSymbolAddress((void**)&wolo, g_wolo);
    cudaGetSymbolAddress((void**)&aohi, g_aohi);
    cudaGetSymbolAddress((void**)&aolo, g_aolo);
    cudaGetSymbolAddress((void**)&qhi,  g_qhi);
    cudaGetSymbolAddress((void**)&qlo,  g_qlo);
    cudaGetSymbolAddress((void**)&khi,  g_khi);
    cudaGetSymbolAddress((void**)&klo,  g_klo);
    cudaGetSymbolAddress((void**)&vhi,  g_vhi);
    cudaGetSymbolAddress((void**)&vlo,  g_vlo);

    cudaFuncSetAttribute(gemm_mma, cudaFuncAttributeMaxDynamicSharedMemorySize, MT_SMEM);
    cudaFuncSetAttribute(attn2, cudaFuncAttributeMaxDynamicSharedMemorySize, A2_SMEM);

    // 0) merged preprocessing: splits + cache copies
    prep<<<(P_N3 + 255) / 256, 256>>>((const float4*)x, (const float4*)Wqkv,
                                      (const float4*)Wo, (const float4*)kci,
                                      (const float4*)vci,
                                      (uint2*)xhi, (uint2*)xlo,
                                      (uint2*)wqhi, (uint2*)wqlo,
                                      (uint2*)wohi, (uint2*)wolo,
                                      (float4*)kc, (float4*)vc);

    // 1) QKV projection (tensor cores, 128x128 tiles, 3-stage)
    gemm_mma<<<dim3(QKV_N / 128, NTOK / 128), 256, MT_SMEM>>>(
        xhi, xlo, wqhi, wqlo, bqkv, qkv, NTOK, QKV_N, HID_);

    // 2) Merged RoPE + split + scatter (Q blocks + KV blocks, one launch)
    ropeall<<<ROPE_QB + ROPE_KB, 256>>>(qkv, cosp, sinp, slot,
                                        kc, vc, qhi, qlo, khi, klo, vhi, vlo);

    // 3) Tensor-core flash attention (heavy CTAs first)
    attn2<<<dim3(S_ / 128, H_, B_), 256, A2_SMEM>>>(qhi, qlo, khi, klo, vhi, vlo,
                                                    aohi, aolo);

    // 4) Output projection (tensor cores)
    gemm_mma<<<dim3(HID_ / 128, NTOK / 128), 256, MT_SMEM>>>(
        aohi, aolo, wohi, wolo, nullptr, out, NTOK, HID_, HID_);
}

// round 12
// speedup vs baseline: 1.2967x; 1.1977x over previous
#include <cuda_runtime.h>
#include <cuda_bf16.h>
#include <cuda_fp16.h>
#include <math.h>
#include <stdint.h>

// Problem constants
#define B_    4
#define S_    2048
#define HID_  1536
#define H_    12
#define HKV_  2
#define D_    128
#define NGROUPS_ 6
#define NSLOTS_ 16384
#define NTOK  (B_ * S_)            // 8192
#define QKV_N (H_*D_ + 2*HKV_*D_)  // 2048

// Scratch (device globals; allocation in kernel_launch is forbidden)
__device__ float g_qkv[(size_t)NTOK * QKV_N];   // 64 MB
__device__ __nv_bfloat16 g_xhi [(size_t)NTOK * HID_];
__device__ __nv_bfloat16 g_xlo [(size_t)NTOK * HID_];
__device__ __nv_bfloat16 g_wqhi[(size_t)QKV_N * HID_];
__device__ __nv_bfloat16 g_wqlo[(size_t)QKV_N * HID_];
__device__ __half        g_wof [(size_t)HID_ * HID_];    // fp16 Wo
__device__ __half        g_aof [(size_t)NTOK * HID_];    // fp16 attention output
// Attention operand buffers (hi/lo splits)
__device__ __nv_bfloat16 g_qhi[(size_t)B_ * H_ * S_ * D_];
__device__ __nv_bfloat16 g_qlo[(size_t)B_ * H_ * S_ * D_];
__device__ __nv_bfloat16 g_khi[(size_t)B_ * HKV_ * S_ * D_];
__device__ __nv_bfloat16 g_klo[(size_t)B_ * HKV_ * S_ * D_];
__device__ __nv_bfloat16 g_vhi[(size_t)B_ * HKV_ * D_ * S_];  // transposed [d][s]
__device__ __nv_bfloat16 g_vlo[(size_t)B_ * HKV_ * D_ * S_];

// ---------------------------------------------------------------------------
// Portable PTX helpers
// ---------------------------------------------------------------------------
__device__ __forceinline__ uint32_t s2u(const void* p) {
    uint32_t a;
    asm("{ .reg .u64 t; cvta.to.shared.u64 t, %1; cvt.u32.u64 %0, t; }"
        : "=r"(a) : "l"(p));
    return a;
}

#define CP_ASYNC16(dst, src) \
    asm volatile("cp.async.cg.shared.global [%0], [%1], 16;" \
                 :: "r"(dst), "l"(src))
#define CP_COMMIT() asm volatile("cp.async.commit_group;")
#define CP_WAIT1()  asm volatile("cp.async.wait_group 1;")
#define CP_WAIT0()  asm volatile("cp.async.wait_group 0;")

#define LDSM4(r0, r1, r2, r3, addr) \
    asm volatile("ldmatrix.sync.aligned.m8n8.x4.shared.b16 {%0,%1,%2,%3}, [%4];" \
                 : "=r"(r0), "=r"(r1), "=r"(r2), "=r"(r3) : "r"(addr))

#define MMA16816(d, a, b) \
    asm volatile("mma.sync.aligned.m16n8k16.row.col.f32.bf16.bf16.f32 " \
                 "{%0,%1,%2,%3}, {%4,%5,%6,%7}, {%8,%9}, {%0,%1,%2,%3};" \
                 : "+f"((d)[0]), "+f"((d)[1]), "+f"((d)[2]), "+f"((d)[3]) \
                 : "r"((a)[0]), "r"((a)[1]), "r"((a)[2]), "r"((a)[3]), \
                   "r"((b)[0]), "r"((b)[1]))

#define MMAF16(d, a, b) \
    asm volatile("mma.sync.aligned.m16n8k16.row.col.f32.f16.f16.f32 " \
                 "{%0,%1,%2,%3}, {%4,%5,%6,%7}, {%8,%9}, {%0,%1,%2,%3};" \
                 : "+f"((d)[0]), "+f"((d)[1]), "+f"((d)[2]), "+f"((d)[3]) \
                 : "r"((a)[0]), "r"((a)[1]), "r"((a)[2]), "r"((a)[3]), \
                   "r"((b)[0]), "r"((b)[1]))

__device__ __forceinline__ float ex2f(float x) {
    float r;
    asm("ex2.approx.ftz.f32 %0, %1;" : "=f"(r) : "f"(x));
    return r;
}

__device__ __forceinline__ uint32_t packbf(float a, float b) {
    __nv_bfloat162 t = __floats2bfloat162_rn(a, b);
    return *(uint32_t*)&t;
}

// gemm smem swizzle (64B rows, 4x 16B chunks)
__device__ __forceinline__ uint32_t swz(int r, int c) {
    return (uint32_t)(r * 64 + ((c ^ ((r >> 1) & 3)) << 4));
}
// 256B rows, 16x 16B chunks
__device__ __forceinline__ uint32_t swzq(int r, int c) {
    return (uint32_t)(r * 256 + ((c ^ (r & 7)) << 4));
}
// 128B rows, 8x 16B chunks
__device__ __forceinline__ uint32_t swzv(int r, int c) {
    return (uint32_t)(r * 128 + ((c ^ (r & 7)) << 4));
}

__device__ __forceinline__ void split1(float x, __nv_bfloat16& h, __nv_bfloat16& l) {
    h = __float2bfloat16(x);
    l = __float2bfloat16(x - __bfloat162float(h));
}

__device__ __forceinline__ uint32_t pack2(__nv_bfloat16 a, __nv_bfloat16 b) {
    return (uint32_t)__bfloat16_as_ushort(a) | ((uint32_t)__bfloat16_as_ushort(b) << 16);
}

__device__ __forceinline__ void split4(float4 v, uint2* hi, uint2* lo) {
    __nv_bfloat16 h0, h1, h2, h3, l0, l1, l2, l3;
    split1(v.x, h0, l0); split1(v.y, h1, l1);
    split1(v.z, h2, l2); split1(v.w, h3, l3);
    uint2 hv, lv;
    hv.x = pack2(h0, h1); hv.y = pack2(h2, h3);
    lv.x = pack2(l0, l1); lv.y = pack2(l2, l3);
    *hi = hv; *lo = lv;
}

// ---------------------------------------------------------------------------
// Merged preprocessing: splits of x/Wqkv (bf16 hi/lo), Wo (fp16) + cache copies.
// ---------------------------------------------------------------------------
#define P_N0 (NTOK * HID_ / 4)                       // x
#define P_N1 (P_N0 + QKV_N * HID_ / 4)               // + Wqkv
#define P_N2 (P_N1 + HID_ * HID_ / 4)                // + Wo
#define P_N3 (P_N2 + NSLOTS_ * HKV_ * D_ / 4)        // + caches

__global__ void prep(const float4* __restrict__ x, const float4* __restrict__ wq,
                     const float4* __restrict__ wo,
                     const float4* __restrict__ kci, const float4* __restrict__ vci,
                     uint2* __restrict__ xhi, uint2* __restrict__ xlo,
                     uint2* __restrict__ wqhi, uint2* __restrict__ wqlo,
                     uint2* __restrict__ wof,
                     float4* __restrict__ kc, float4* __restrict__ vc)
{
    int i = blockIdx.x * blockDim.x + threadIdx.x;
    if (i < P_N0) {
        split4(x[i], xhi + i, xlo + i);
    } else if (i < P_N1) {
        int j = i - P_N0;
        split4(wq[j], wqhi + j, wqlo + j);
    } else if (i < P_N2) {
        int j = i - P_N1;
        float4 v = wo[j];
        __half2 a = __floats2half2_rn(v.x, v.y);
        __half2 b = __floats2half2_rn(v.z, v.w);
        uint2 o;
        o.x = *(uint32_t*)&a; o.y = *(uint32_t*)&b;
        wof[j] = o;
    } else if (i < P_N3) {
        int j = i - P_N2;
        kc[j] = kci[j];
        vc[j] = vci[j];
    }
}

// ---------------------------------------------------------------------------
// Compensated bf16 GEMM (128x128 CTA, 32x64 warp tile, 3-stage).
// C = Ahi*Bhi^T + Ahi*Blo^T + Alo*Bhi^T (+bias)
// ---------------------------------------------------------------------------
#define MT_TILE   8192
#define MT_STAGE  32768
#define MT_SMEM   (3 * MT_STAGE)   // 96 KB -> 2 CTAs/SM

__device__ __forceinline__ void mt_stage_load(
    const __nv_bfloat16* __restrict__ Ahi, const __nv_bfloat16* __restrict__ Alo,
    const __nv_bfloat16* __restrict__ Bhi, const __nv_bfloat16* __restrict__ Blo,
    int m0, int n0, int K, int k0, uint32_t sstage, int tid)
{
    #pragma unroll
    for (int it = 0; it < 8; it++) {
        int idx = tid + it * 256;
        int t   = idx >> 9;
        int rem = idx & 511;
        int r   = rem >> 2;
        int c   = rem & 3;
        const __nv_bfloat16* base = (t == 0) ? Ahi : (t == 1) ? Alo
                                  : (t == 2) ? Bhi : Blo;
        int row0 = (t < 2) ? m0 : n0;
        const char* src = (const char*)(base + (size_t)(row0 + r) * K + k0) + c * 16;
        uint32_t dst = sstage + (uint32_t)t * MT_TILE + swz(r, c);
        CP_ASYNC16(dst, src);
    }
}

__global__ __launch_bounds__(256)
void gemm_mma(const __nv_bfloat16* __restrict__ Ahi, const __nv_bfloat16* __restrict__ Alo,
              const __nv_bfloat16* __restrict__ Bhi, const __nv_bfloat16* __restrict__ Blo,
              const float* __restrict__ bias, float* __restrict__ C,
              int M, int N, int K)
{
    extern __shared__ char smg[];
    uint32_t sb = s2u(smg);
    int tid = threadIdx.x;
    int wid = tid >> 5, lane = tid & 31;
    int wm = wid & 3, wn = wid >> 2;
    int mbase = wm * 32, nbase = wn * 64;
    int m0 = blockIdx.y * 128, n0 = blockIdx.x * 128;

    float acc[2][8][4];
    #pragma unroll
    for (int i = 0; i < 2; i++)
        #pragma unroll
        for (int j = 0; j < 8; j++)
            #pragma unroll
            for (int q = 0; q < 4; q++) acc[i][j][q] = 0.f;

    const int nkt = K >> 5;

    mt_stage_load(Ahi, Alo, Bhi, Blo, m0, n0, K, 0, sb, tid);
    CP_COMMIT();
    mt_stage_load(Ahi, Alo, Bhi, Blo, m0, n0, K, 32, sb + MT_STAGE, tid);
    CP_COMMIT();

    int lrow = lane & 15;
    int lsel = lane >> 4;

    for (int kt = 0; kt < nkt; kt++) {
        if (kt == nkt - 1) { CP_WAIT0(); } else { CP_WAIT1(); }
        __syncthreads();
        if (kt + 2 < nkt) {
            mt_stage_load(Ahi, Alo, Bhi, Blo, m0, n0, K, (kt + 2) << 5,
                          sb + (uint32_t)((kt + 2) % 3) * MT_STAGE, tid);
            CP_COMMIT();
        }
        uint32_t sbuf = sb + (uint32_t)(kt % 3) * MT_STAGE;

        #pragma unroll
        for (int ks = 0; ks < 2; ks++) {
            int kc = ks * 2;
            uint32_t ah[2][4], al[2][4], bh[8][2], bl[8][2];
            #pragma unroll
            for (int f = 0; f < 2; f++) {
                int r = mbase + f * 16 + lrow;
                int c = kc + lsel;
                LDSM4(ah[f][0], ah[f][1], ah[f][2], ah[f][3], sbuf + swz(r, c));
                LDSM4(al[f][0], al[f][1], al[f][2], al[f][3],
                      sbuf + MT_TILE + swz(r, c));
            }
            #pragma unroll
            for (int g = 0; g < 4; g++) {
                int r = nbase + g * 16 + lrow;
                int c = kc + lsel;
                uint32_t r0, r1, r2, r3;
                LDSM4(r0, r1, r2, r3, sbuf + 2 * MT_TILE + swz(r, c));
                bh[2*g][0] = r0; bh[2*g][1] = r2;
                bh[2*g+1][0] = r1; bh[2*g+1][1] = r3;
                LDSM4(r0, r1, r2, r3, sbuf + 3 * MT_TILE + swz(r, c));
                bl[2*g][0] = r0; bl[2*g][1] = r2;
                bl[2*g+1][0] = r1; bl[2*g+1][1] = r3;
            }
            #pragma unroll
            for (int mi = 0; mi < 2; mi++)
                #pragma unroll
                for (int nj = 0; nj < 8; nj++) {
                    MMA16816(acc[mi][nj], ah[mi], bh[nj]);
                    MMA16816(acc[mi][nj], ah[mi], bl[nj]);
                    MMA16816(acc[mi][nj], al[mi], bh[nj]);
                }
        }
    }

    int erow = lane >> 2;
    int ecol = (lane & 3) * 2;
    #pragma unroll
    for (int mi = 0; mi < 2; mi++) {
        #pragma unroll
        for (int nj = 0; nj < 8; nj++) {
            int col = n0 + nbase + nj * 8 + ecol;
            float b0 = bias ? bias[col]     : 0.f;
            float b1 = bias ? bias[col + 1] : 0.f;
            int r0 = m0 + mbase + mi * 16 + erow;
            float2 v0 = make_float2(acc[mi][nj][0] + b0, acc[mi][nj][1] + b1);
            float2 v1 = make_float2(acc[mi][nj][2] + b0, acc[mi][nj][3] + b1);
            *(float2*)(C + (size_t)r0 * N + col)       = v0;
            *(float2*)(C + (size_t)(r0 + 8) * N + col) = v1;
        }
    }
}

// ---------------------------------------------------------------------------
// Single-pass fp16 GEMM (out projection): C = A * B^T, fp32 accumulate.
// 128x128 CTA, 32x64 warp tile, 3-stage (16 KB/stage, 48 KB total).
// ---------------------------------------------------------------------------
#define F_TILE  8192
#define F_STAGE 16384
#define F_SMEM  (3 * F_STAGE)   // 48 KB

__device__ __forceinline__ void f16_stage_load(
    const __half* __restrict__ A, const __half* __restrict__ B,
    int m0, int n0, int K, int k0, uint32_t st, int tid)
{
    #pragma unroll
    for (int it = 0; it < 4; it++) {
        int idx = tid + it * 256;      // 0..1023
        int t   = idx >> 9;            // 0: A, 1: B
        int rem = idx & 511;
        int r   = rem >> 2;
        int c   = rem & 3;
        const __half* base = t ? B : A;
        int row0 = t ? n0 : m0;
        const char* src = (const char*)(base + (size_t)(row0 + r) * K + k0) + c * 16;
        CP_ASYNC16(st + (uint32_t)t * F_TILE + swz(r, c), src);
    }
}

__global__ __launch_bounds__(256)
void gemm_f16(const __half* __restrict__ A, const __half* __restrict__ B,
              float* __restrict__ C, int M, int N, int K)
{
    extern __shared__ char smf[];
    uint32_t sb = s2u(smf);
    int tid = threadIdx.x;
    int wid = tid >> 5, lane = tid & 31;
    int wm = wid & 3, wn = wid >> 2;
    int mbase = wm * 32, nbase = wn * 64;
    int m0 = blockIdx.y * 128, n0 = blockIdx.x * 128;

    float acc[2][8][4];
    #pragma unroll
    for (int i = 0; i < 2; i++)
        #pragma unroll
        for (int j = 0; j < 8; j++)
            #pragma unroll
            for (int q = 0; q < 4; q++) acc[i][j][q] = 0.f;

    const int nkt = K >> 5;

    f16_stage_load(A, B, m0, n0, K, 0, sb, tid);
    CP_COMMIT();
    f16_stage_load(A, B, m0, n0, K, 32, sb + F_STAGE, tid);
    CP_COMMIT();

    int lrow = lane & 15;
    int lsel = lane >> 4;

    for (int kt = 0; kt < nkt; kt++) {
        if (kt == nkt - 1) { CP_WAIT0(); } else { CP_WAIT1(); }
        __syncthreads();
        if (kt + 2 < nkt) {
            f16_stage_load(A, B, m0, n0, K, (kt + 2) << 5,
                           sb + (uint32_t)((kt + 2) % 3) * F_STAGE, tid);
            CP_COMMIT();
        }
        uint32_t sbuf = sb + (uint32_t)(kt % 3) * F_STAGE;

        #pragma unroll
        for (int ks = 0; ks < 2; ks++) {
            int kc = ks * 2;
            uint32_t ah[2][4], bh[8][2];
            #pragma unroll
            for (int f = 0; f < 2; f++) {
                int r = mbase + f * 16 + lrow;
                int c = kc + lsel;
                LDSM4(ah[f][0], ah[f][1], ah[f][2], ah[f][3], sbuf + swz(r, c));
            }
            #pragma unroll
            for (int g = 0; g < 4; g++) {
                int r = nbase + g * 16 + lrow;
                int c = kc + lsel;
                uint32_t r0, r1, r2, r3;
                LDSM4(r0, r1, r2, r3, sbuf + F_TILE + swz(r, c));
                bh[2*g][0] = r0; bh[2*g][1] = r2;
                bh[2*g+1][0] = r1; bh[2*g+1][1] = r3;
            }
            #pragma unroll
            for (int mi = 0; mi < 2; mi++)
                #pragma unroll
                for (int nj = 0; nj < 8; nj++)
                    MMAF16(acc[mi][nj], ah[mi], bh[nj]);
        }
    }

    int erow = lane >> 2;
    int ecol = (lane & 3) * 2;
    #pragma unroll
    for (int mi = 0; mi < 2; mi++) {
        #pragma unroll
        for (int nj = 0; nj < 8; nj++) {
            int col = n0 + nbase + nj * 8 + ecol;
            int r0 = m0 + mbase + mi * 16 + erow;
            *(float2*)(C + (size_t)r0 * N + col) =
                make_float2(acc[mi][nj][0], acc[mi][nj][1]);
            *(float2*)(C + (size_t)(r0 + 8) * N + col) =
                make_float2(acc[mi][nj][2], acc[mi][nj][3]);
        }
    }
}

// ---------------------------------------------------------------------------
// Merged RoPE kernel: blocks [0, QB) do Q rope+split; [QB, QB+KB) do KV work.
// ---------------------------------------------------------------------------
#define ROPE_QB ((NTOK * H_ * 16) / 256)     // 6144 blocks
#define ROPE_KB (B_ * HKV_ * (S_ / 64))      // 256 blocks

__global__ __launch_bounds__(256)
void ropeall(const float* __restrict__ qkv, const float* __restrict__ cosp,
             const float* __restrict__ sinp, const int* __restrict__ slot_mapping,
             float* __restrict__ kc, float* __restrict__ vc,
             __nv_bfloat16* __restrict__ qhi, __nv_bfloat16* __restrict__ qlo,
             __nv_bfloat16* __restrict__ khi, __nv_bfloat16* __restrict__ klo,
             __nv_bfloat16* __restrict__ vhi, __nv_bfloat16* __restrict__ vlo)
{
    __shared__ float vbuf[64][132];
    int tid = threadIdx.x;

    if (blockIdx.x < ROPE_QB) {
        int idx = blockIdx.x * 256 + tid;
        int t  = idx / (H_ * 16);
        int r  = idx - t * (H_ * 16);
        int h  = r >> 4, d4 = r & 15;
        int d  = d4 * 4;
        int b  = t >> 11, s = t & 2047;

        const float* rowp = qkv + (size_t)t * QKV_N + h * D_;
        float4 x1 = *(const float4*)(rowp + d);
        float4 x2 = *(const float4*)(rowp + d + 64);
        const float* cp = cosp + (size_t)t * D_;
        const float* sp = sinp + (size_t)t * D_;
        float4 c1 = *(const float4*)(cp + d),      s1 = *(const float4*)(sp + d);
        float4 c2 = *(const float4*)(cp + d + 64), s2 = *(const float4*)(sp + d + 64);

        const float qs = 0.08838834764831845f * 1.4426950408889634f;
        float o1[4], o2[4];
        o1[0] = (x1.x * c1.x - x2.x * s1.x) * qs;
        o1[1] = (x1.y * c1.y - x2.y * s1.y) * qs;
        o1[2] = (x1.z * c1.z - x2.z * s1.z) * qs;
        o1[3] = (x1.w * c1.w - x2.w * s1.w) * qs;
        o2[0] = (x2.x * c2.x + x1.x * s2.x) * qs;
        o2[1] = (x2.y * c2.y + x1.y * s2.y) * qs;
        o2[2] = (x2.z * c2.z + x1.z * s2.z) * qs;
        o2[3] = (x2.w * c2.w + x1.w * s2.w) * qs;

        __nv_bfloat16 hh[4], ll[4];
        uint2 hv, lv;
        size_t o = ((size_t)(b * H_ + h) * S_ + s) * D_;
        #pragma unroll
        for (int j = 0; j < 4; j++) split1(o1[j], hh[j], ll[j]);
        hv.x = pack2(hh[0], hh[1]); hv.y = pack2(hh[2], hh[3]);
        lv.x = pack2(ll[0], ll[1]); lv.y = pack2(ll[2], ll[3]);
        *(uint2*)(qhi + o + d) = hv;
        *(uint2*)(qlo + o + d) = lv;
        #pragma unroll
        for (int j = 0; j < 4; j++) split1(o2[j], hh[j], ll[j]);
        hv.x = pack2(hh[0], hh[1]); hv.y = pack2(hh[2], hh[3]);
        lv.x = pack2(ll[0], ll[1]); lv.y = pack2(ll[2], ll[3]);
        *(uint2*)(qhi + o + d + 64) = hv;
        *(uint2*)(qlo + o + d + 64) = lv;
        return;
    }

    int blk = blockIdx.x - ROPE_QB;
    int st64 = blk & 31;
    int kvh  = (blk >> 5) & 1;
    int b    = blk >> 6;
    int s0 = st64 * 64;

    #pragma unroll
    for (int it = 0; it < 4; it++) {
        int idx = tid + it * 256;
        int r = idx >> 4, d4 = idx & 15;
        int d = d4 * 4;
        int t = b * S_ + s0 + r;
        const float* rowp = qkv + (size_t)t * QKV_N + H_*D_ + kvh * D_;
        float4 x1 = *(const float4*)(rowp + d);
        float4 x2 = *(const float4*)(rowp + d + 64);
        const float* cp = cosp + (size_t)t * D_;
        const float* sp = sinp + (size_t)t * D_;
        float4 c1 = *(const float4*)(cp + d),      s1 = *(const float4*)(sp + d);
        float4 c2 = *(const float4*)(cp + d + 64), s2 = *(const float4*)(sp + d + 64);
        float4 o1, o2;
        o1.x = x1.x * c1.x - x2.x * s1.x;
        o1.y = x1.y * c1.y - x2.y * s1.y;
        o1.z = x1.z * c1.z - x2.z * s1.z;
        o1.w = x1.w * c1.w - x2.w * s1.w;
        o2.x = x2.x * c2.x + x1.x * s2.x;
        o2.y = x2.y * c2.y + x1.y * s2.y;
        o2.z = x2.z * c2.z + x1.z * s2.z;
        o2.w = x2.w * c2.w + x1.w * s2.w;

        int slot = slot_mapping[t];
        float* kcp = kc + (size_t)slot * (HKV_*D_) + kvh * D_;
        *(float4*)(kcp + d)      = o1;
        *(float4*)(kcp + d + 64) = o2;

        __nv_bfloat16 hh[4], ll[4];
        uint2 hv, lv;
        size_t ko = ((size_t)(b * HKV_ + kvh) * S_ + s0 + r) * D_;
        split1(o1.x, hh[0], ll[0]); split1(o1.y, hh[1], ll[1]);
        split1(o1.z, hh[2], ll[2]); split1(o1.w, hh[3], ll[3]);
        hv.x = pack2(hh[0], hh[1]); hv.y = pack2(hh[2], hh[3]);
        lv.x = pack2(ll[0], ll[1]); lv.y = pack2(ll[2], ll[3]);
        *(uint2*)(khi + ko + d) = hv;
        *(uint2*)(klo + ko + d) = lv;
        split1(o2.x, hh[0], ll[0]); split1(o2.y, hh[1], ll[1]);
        split1(o2.z, hh[2], ll[2]); split1(o2.w, hh[3], ll[3]);
        hv.x = pack2(hh[0], hh[1]); hv.y = pack2(hh[2], hh[3]);
        lv.x = pack2(ll[0], ll[1]); lv.y = pack2(ll[2], ll[3]);
        *(uint2*)(khi + ko + d + 64) = hv;
        *(uint2*)(klo + ko + d + 64) = lv;
    }

    #pragma unroll
    for (int it = 0; it < 8; it++) {
        int idx = tid + it * 256;
        int r = idx >> 5, c4 = idx & 31;
        int t = b * S_ + s0 + r;
        float4 vv = *(const float4*)(qkv + (size_t)t * QKV_N
                                     + H_*D_ + HKV_*D_ + kvh * D_ + c4 * 4);
        int slot = slot_mapping[t];
        *(float4*)(vc + (size_t)slot * (HKV_*D_) + kvh * D_ + c4 * 4) = vv;
        vbuf[r][c4*4+0] = vv.x; vbuf[r][c4*4+1] = vv.y;
        vbuf[r][c4*4+2] = vv.z; vbuf[r][c4*4+3] = vv.w;
    }
    __syncthreads();

    int d = tid >> 1, half = tid & 1;
    uint32_t hw[16], lw[16];
    #pragma unroll
    for (int j = 0; j < 16; j++) {
        float x0 = vbuf[half*32 + 2*j    ][d];
        float x1 = vbuf[half*32 + 2*j + 1][d];
        __nv_bfloat16 ha, hb, la, lb;
        split1(x0, ha, la); split1(x1, hb, lb);
        hw[j] = pack2(ha, hb);
        lw[j] = pack2(la, lb);
    }
    size_t o = ((size_t)(b * HKV_ + kvh) * D_ + d) * S_ + s0 + half * 32;
    #pragma unroll
    for (int q = 0; q < 4; q++) {
        *(uint4*)(vhi + o + q * 8) = *(uint4*)&hw[q * 4];
        *(uint4*)(vlo + o + q * 8) = *(uint4*)&lw[q * 4];
    }
}

// ---------------------------------------------------------------------------
// Tensor-core flash attention. BLOCK_M=128 (8 warps x m16), BLOCK_N=64, D=128.
// Heavy-first scheduling; writes fp16 output directly.
// ---------------------------------------------------------------------------
#define A2_QBYTES 65536
#define A2_STAGE  65536
#define A2_SMEM   (A2_QBYTES + 2 * A2_STAGE)  // 196608

__global__ __launch_bounds__(256, 1)
void attn2(const __nv_bfloat16* __restrict__ qhi, const __nv_bfloat16* __restrict__ qlo,
           const __nv_bfloat16* __restrict__ khi, const __nv_bfloat16* __restrict__ klo,
           const __nv_bfloat16* __restrict__ vhi, const __nv_bfloat16* __restrict__ vlo,
           __half* __restrict__ aof)
{
    extern __shared__ char sm2[];
    uint32_t sb = s2u(sm2);
    int qt = (int)gridDim.x - 1 - (int)blockIdx.x;   // heavy-first
    int h = blockIdx.y, b = blockIdx.z;
    int kvh = h / NGROUPS_;
    int q0 = qt * 128;
    int tid = threadIdx.x, wid = tid >> 5, lane = tid & 31;
    int lrow = lane & 15, lsel = lane >> 4;

    const char* qh_base = (const char*)(qhi + ((size_t)(b * H_ + h) * S_ + q0) * D_);
    const char* ql_base = (const char*)(qlo + ((size_t)(b * H_ + h) * S_ + q0) * D_);
    const char* kh_base = (const char*)(khi + ((size_t)(b * HKV_ + kvh) * S_) * D_);
    const char* kl_base = (const char*)(klo + ((size_t)(b * HKV_ + kvh) * S_) * D_);
    const char* vh_base = (const char*)(vhi + ((size_t)(b * HKV_ + kvh) * D_) * S_);
    const char* vl_base = (const char*)(vlo + ((size_t)(b * HKV_ + kvh) * D_) * S_);

    #pragma unroll
    for (int it = 0; it < 8; it++) {
        int idx = tid + it * 256;
        int r = idx >> 4, c = idx & 15;
        CP_ASYNC16(sb + swzq(r, c),          qh_base + r * 256 + c * 16);
        CP_ASYNC16(sb + 32768 + swzq(r, c),  ql_base + r * 256 + c * 16);
    }

    const int nt = 2 * qt + 2;

    auto load_kv = [&](int t, int st_i) {
        uint32_t st = sb + A2_QBYTES + (uint32_t)st_i * A2_STAGE;
        int k0 = t * 64;
        #pragma unroll
        for (int it = 0; it < 4; it++) {
            int idx = tid + it * 256;
            int r = idx >> 4, c = idx & 15;
            CP_ASYNC16(st + swzq(r, c),          kh_base + (size_t)(k0 + r) * 256 + c * 16);
            CP_ASYNC16(st + 16384 + swzq(r, c),  kl_base + (size_t)(k0 + r) * 256 + c * 16);
        }
        #pragma unroll
        for (int it = 0; it < 4; it++) {
            int idx = tid + it * 256;
            int r = idx >> 3, c = idx & 7;
            CP_ASYNC16(st + 32768 + swzv(r, c),
                       vh_base + (size_t)r * (S_ * 2) + k0 * 2 + c * 16);
            CP_ASYNC16(st + 49152 + swzv(r, c),
                       vl_base + (size_t)r * (S_ * 2) + k0 * 2 + c * 16);
        }
    };

    load_kv(0, 0);
    CP_COMMIT();

    float oacc[16][4];
    #pragma unroll
    for (int i = 0; i < 16; i++)
        #pragma unroll
        for (int j = 0; j < 4; j++) oacc[i][j] = 0.f;
    float m0 = -1e30f, m1 = -1e30f, l0 = 0.f, l1 = 0.f;

    for (int t = 0; t < nt; t++) {
        uint32_t st = sb + A2_QBYTES + (uint32_t)(t & 1) * A2_STAGE;
        if (t + 1 < nt) {
            load_kv(t + 1, (t + 1) & 1);
            CP_COMMIT();
            CP_WAIT1();
        } else {
            CP_WAIT0();
        }
        __syncthreads();

        float sacc[8][4];
        #pragma unroll
        for (int i = 0; i < 8; i++)
            #pragma unroll
            for (int j = 0; j < 4; j++) sacc[i][j] = 0.f;

        #pragma unroll
        for (int kc = 0; kc < 8; kc++) {
            uint32_t qa[4], qla[4];
            LDSM4(qa[0], qa[1], qa[2], qa[3],
                  sb + swzq(wid * 16 + lrow, kc * 2 + lsel));
            LDSM4(qla[0], qla[1], qla[2], qla[3],
                  sb + 32768 + swzq(wid * 16 + lrow, kc * 2 + lsel));
            uint32_t bh[8][2], bl[8][2];
            #pragma unroll
            for (int g = 0; g < 4; g++) {
                uint32_t r0, r1, r2, r3;
                LDSM4(r0, r1, r2, r3, st + swzq(g * 16 + lrow, kc * 2 + lsel));
                bh[2*g][0] = r0; bh[2*g][1] = r2;
                bh[2*g+1][0] = r1; bh[2*g+1][1] = r3;
                LDSM4(r0, r1, r2, r3, st + 16384 + swzq(g * 16 + lrow, kc * 2 + lsel));
                bl[2*g][0] = r0; bl[2*g][1] = r2;
                bl[2*g+1][0] = r1; bl[2*g+1][1] = r3;
            }
            #pragma unroll
            for (int nj = 0; nj < 8; nj++) {
                MMA16816(sacc[nj], qa, bh[nj]);
                MMA16816(sacc[nj], qa, bl[nj]);
                MMA16816(sacc[nj], qla, bh[nj]);
            }
        }

        int k0 = t * 64;
        if (t >= nt - 2) {
            int qr0 = q0 + wid * 16 + (lane >> 2);
            int qr1 = qr0 + 8;
            #pragma unroll
            for (int nj = 0; nj < 8; nj++) {
                int kcol = k0 + nj * 8 + (lane & 3) * 2;
                if (kcol     > qr0) sacc[nj][0] = -1e30f;
                if (kcol + 1 > qr0) sacc[nj][1] = -1e30f;
                if (kcol     > qr1) sacc[nj][2] = -1e30f;
                if (kcol + 1 > qr1) sacc[nj][3] = -1e30f;
            }
        }

        float mx0 = -1e30f, mx1 = -1e30f;
        #pragma unroll
        for (int nj = 0; nj < 8; nj++) {
            mx0 = fmaxf(mx0, fmaxf(sacc[nj][0], sacc[nj][1]));
            mx1 = fmaxf(mx1, fmaxf(sacc[nj][2], sacc[nj][3]));
        }
        mx0 = fmaxf(mx0, __shfl_xor_sync(0xffffffffu, mx0, 1));
        mx0 = fmaxf(mx0, __shfl_xor_sync(0xffffffffu, mx0, 2));
        mx1 = fmaxf(mx1, __shfl_xor_sync(0xffffffffu, mx1, 1));
        mx1 = fmaxf(mx1, __shfl_xor_sync(0xffffffffu, mx1, 2));
        float nm0 = fmaxf(m0, mx0), nm1 = fmaxf(m1, mx1);
        float f0 = ex2f(m0 - nm0), f1 = ex2f(m1 - nm1);
        m0 = nm0; m1 = nm1;

        uint32_t ph[4][4], pl[4][4];
        float rs0 = 0.f, rs1 = 0.f;
        #pragma unroll
        for (int j = 0; j < 4; j++) {
            float pe0 = ex2f(sacc[2*j][0] - nm0);
            float pe1 = ex2f(sacc[2*j][1] - nm0);
            float pe2 = ex2f(sacc[2*j][2] - nm1);
            float pe3 = ex2f(sacc[2*j][3] - nm1);
            float po0 = ex2f(sacc[2*j+1][0] - nm0);
            float po1 = ex2f(sacc[2*j+1][1] - nm0);
            float po2 = ex2f(sacc[2*j+1][2] - nm1);
            float po3 = ex2f(sacc[2*j+1][3] - nm1);
            rs0 += pe0 + pe1 + po0 + po1;
            rs1 += pe2 + pe3 + po2 + po3;
            ph[j][0] = packbf(pe0, pe1);
            ph[j][1] = packbf(pe2, pe3);
            ph[j][2] = packbf(po0, po1);
            ph[j][3] = packbf(po2, po3);
            __nv_bfloat16 hh; float r, q0r;
            hh = __float2bfloat16(pe0); q0r = pe0 - __bfloat162float(hh);
            hh = __float2bfloat16(pe1); r = pe1 - __bfloat162float(hh);
            pl[j][0] = packbf(q0r, r);
            hh = __float2bfloat16(pe2); q0r = pe2 - __bfloat162float(hh);
            hh = __float2bfloat16(pe3); r = pe3 - __bfloat162float(hh);
            pl[j][1] = packbf(q0r, r);
            hh = __float2bfloat16(po0); q0r = po0 - __bfloat162float(hh);
            hh = __float2bfloat16(po1); r = po1 - __bfloat162float(hh);
            pl[j][2] = packbf(q0r, r);
            hh = __float2bfloat16(po2); q0r = po2 - __bfloat162float(hh);
            hh = __float2bfloat16(po3); r = po3 - __bfloat162float(hh);
            pl[j][3] = packbf(q0r, r);
        }
        rs0 += __shfl_xor_sync(0xffffffffu, rs0, 1);
        rs0 += __shfl_xor_sync(0xffffffffu, rs0, 2);
        rs1 += __shfl_xor_sync(0xffffffffu, rs1, 1);
        rs1 += __shfl_xor_sync(0xffffffffu, rs1, 2);
        l0 = l0 * f0 + rs0;
        l1 = l1 * f1 + rs1;
        #pragma unroll
        for (int nj = 0; nj < 16; nj++) {
            oacc[nj][0] *= f0; oacc[nj][1] *= f0;
            oacc[nj][2] *= f1; oacc[nj][3] *= f1;
        }

        #pragma unroll
        for (int j = 0; j < 4; j++) {
            #pragma unroll
            for (int g = 0; g < 8; g++) {
                uint32_t r0, r1, r2, r3, s0r, s1r, s2r, s3r;
                LDSM4(r0, r1, r2, r3, st + 32768 + swzv(g * 16 + lrow, j * 2 + lsel));
                LDSM4(s0r, s1r, s2r, s3r, st + 49152 + swzv(g * 16 + lrow, j * 2 + lsel));
                uint32_t vh0[2] = {r0, r2}, vh1[2] = {r1, r3};
                uint32_t vl0[2] = {s0r, s2r}, vl1[2] = {s1r, s3r};
                MMA16816(oacc[2*g],   ph[j], vh0);
                MMA16816(oacc[2*g],   ph[j], vl0);
                MMA16816(oacc[2*g],   pl[j], vh0);
                MMA16816(oacc[2*g+1], ph[j], vh1);
                MMA16816(oacc[2*g+1], ph[j], vl1);
                MMA16816(oacc[2*g+1], pl[j], vh1);
            }
        }
        __syncthreads();
    }

    // epilogue: write fp16 directly
    float inv0 = 1.f / l0, inv1 = 1.f / l1;
    int r0g = q0 + wid * 16 + (lane >> 2);
    #pragma unroll
    for (int nj = 0; nj < 16; nj++) {
        int d = nj * 8 + (lane & 3) * 2;
        __half2 v0 = __floats2half2_rn(oacc[nj][0] * inv0, oacc[nj][1] * inv0);
        __half2 v1 = __floats2half2_rn(oacc[nj][2] * inv1, oacc[nj][3] * inv1);
        *(__half2*)(aof + ((size_t)(b * S_ + r0g)) * HID_ + h * D_ + d)     = v0;
        *(__half2*)(aof + ((size_t)(b * S_ + r0g + 8)) * HID_ + h * D_ + d) = v1;
    }
}

// ---------------------------------------------------------------------------
extern "C" void kernel_launch(void* const* d_in, const int* in_sizes, int n_in,
                              void* d_out, int out_size)
{
    const float* x     = (const float*)d_in[0];
    const float* cosp  = (const float*)d_in[1];
    const float* sinp  = (const float*)d_in[2];
    const float* kci   = (const float*)d_in[3];
    const float* vci   = (const float*)d_in[4];
    const int*   slot  = (const int*)  d_in[5];
    const float* Wqkv  = (const float*)d_in[6];
    const float* bqkv  = (const float*)d_in[7];
    const float* Wo    = (const float*)d_in[8];

    float* out = (float*)d_out;
    float* kc  = out + (size_t)NTOK * HID_;
    float* vc  = kc  + (size_t)NSLOTS_ * HKV_ * D_;

    float* qkv; cudaGetSymbolAddress((void**)&qkv, g_qkv);
    __nv_bfloat16 *xhi, *xlo, *wqhi, *wqlo;
    __nv_bfloat16 *qhi, *qlo, *khi, *klo, *vhi, *vlo;
    __half *wof, *aof;
    cudaGetSymbolAddress((void**)&xhi,  g_xhi);
    cudaGetSymbolAddress((void**)&xlo,  g_xlo);
    cudaGetSymbolAddress((void**)&wqhi, g_wqhi);
    cudaGetSymbolAddress((void**)&wqlo, g_wqlo);
    cudaGetSymbolAddress((void**)&wof,  g_wof);
    cudaGetSymbolAddress((void**)&aof,  g_aof);
    cudaGetSymbolAddress((void**)&qhi,  g_qhi);
    cudaGetSymbolAddress((void**)&qlo,  g_qlo);
    cudaGetSymbolAddress((void**)&khi,  g_khi);
    cudaGetSymbolAddress((void**)&klo,  g_klo);
    cudaGetSymbolAddress((void**)&vhi,  g_vhi);
    cudaGetSymbolAddress((void**)&vlo,  g_vlo);

    cudaFuncSetAttribute(gemm_mma, cudaFuncAttributeMaxDynamicSharedMemorySize, MT_SMEM);
    cudaFuncSetAttribute(gemm_f16, cudaFuncAttributeMaxDynamicSharedMemorySize, F_SMEM);
    cudaFuncSetAttribute(attn2, cudaFuncAttributeMaxDynamicSharedMemorySize, A2_SMEM);

    // 0) merged preprocessing: splits + cache copies
    prep<<<(P_N3 + 255) / 256, 256>>>((const float4*)x, (const float4*)Wqkv,
                                      (const float4*)Wo, (const float4*)kci,
                                      (const float4*)vci,
                                      (uint2*)xhi, (uint2*)xlo,
                                      (uint2*)wqhi, (uint2*)wqlo,
                                      (uint2*)wof,
                                      (float4*)kc, (float4*)vc);

    // 1) QKV projection (compensated bf16 tensor cores)
    gemm_mma<<<dim3(QKV_N / 128, NTOK / 128), 256, MT_SMEM>>>(
        xhi, xlo, wqhi, wqlo, bqkv, qkv, NTOK, QKV_N, HID_);

    // 2) Merged RoPE + split + scatter
    ropeall<<<ROPE_QB + ROPE_KB, 256>>>(qkv, cosp, sinp, slot,
                                        kc, vc, qhi, qlo, khi, klo, vhi, vlo);

    // 3) Tensor-core flash attention (writes fp16 ao)
    attn2<<<dim3(S_ / 128, H_, B_), 256, A2_SMEM>>>(qhi, qlo, khi, klo, vhi, vlo,
                                                    aof);

    // 4) Output projection (single-pass fp16 tensor cores)
    gemm_f16<<<dim3(HID_ / 128, NTOK / 128), 256, F_SMEM>>>(
        aof, wof, out, NTOK, HID_, HID_);
}

// round 13
// speedup vs baseline: 2.4903x; 1.9205x over previous
#include <cuda_runtime.h>
#include <cuda_bf16.h>
#include <cuda_fp16.h>
#include <math.h>
#include <stdint.h>

// Problem constants
#define B_    4
#define S_    2048
#define HID_  1536
#define H_    12
#define HKV_  2
#define D_    128
#define NGROUPS_ 6
#define NSLOTS_ 16384
#define NTOK  (B_ * S_)            // 8192
#define QKV_N (H_*D_ + 2*HKV_*D_)  // 2048

// Scratch (device globals; allocation in kernel_launch is forbidden)
__device__ float  g_qkv[(size_t)NTOK * QKV_N];          // fp32 QKV (rope input)
__device__ __half g_xf [(size_t)NTOK * HID_];           // fp16 x
__device__ __half g_wqf[(size_t)QKV_N * HID_];          // fp16 Wqkv
__device__ __half g_wof[(size_t)HID_ * HID_];           // fp16 Wo
__device__ __half g_aof[(size_t)NTOK * HID_];           // fp16 attention out
__device__ __half g_qf [(size_t)B_ * H_ * S_ * D_];     // fp16 Q (scaled, roped)
__device__ __half g_kf [(size_t)B_ * HKV_ * S_ * D_];   // fp16 K (roped)
__device__ __half g_vf [(size_t)B_ * HKV_ * D_ * S_];   // fp16 V transposed [d][s]

// ---------------------------------------------------------------------------
// Portable PTX helpers
// ---------------------------------------------------------------------------
__device__ __forceinline__ uint32_t s2u(const void* p) {
    uint32_t a;
    asm("{ .reg .u64 t; cvta.to.shared.u64 t, %1; cvt.u32.u64 %0, t; }"
        : "=r"(a) : "l"(p));
    return a;
}

#define CP_ASYNC16(dst, src) \
    asm volatile("cp.async.cg.shared.global [%0], [%1], 16;" \
                 :: "r"(dst), "l"(src))
#define CP_COMMIT() asm volatile("cp.async.commit_group;")
#define CP_WAIT1()  asm volatile("cp.async.wait_group 1;")
#define CP_WAIT0()  asm volatile("cp.async.wait_group 0;")

#define LDSM4(r0, r1, r2, r3, addr) \
    asm volatile("ldmatrix.sync.aligned.m8n8.x4.shared.b16 {%0,%1,%2,%3}, [%4];" \
                 : "=r"(r0), "=r"(r1), "=r"(r2), "=r"(r3) : "r"(addr))

#define MMAF16(d, a, b) \
    asm volatile("mma.sync.aligned.m16n8k16.row.col.f32.f16.f16.f32 " \
                 "{%0,%1,%2,%3}, {%4,%5,%6,%7}, {%8,%9}, {%0,%1,%2,%3};" \
                 : "+f"((d)[0]), "+f"((d)[1]), "+f"((d)[2]), "+f"((d)[3]) \
                 : "r"((a)[0]), "r"((a)[1]), "r"((a)[2]), "r"((a)[3]), \
                   "r"((b)[0]), "r"((b)[1]))

__device__ __forceinline__ float ex2f(float x) {
    float r;
    asm("ex2.approx.ftz.f32 %0, %1;" : "=f"(r) : "f"(x));
    return r;
}

__device__ __forceinline__ uint32_t packh2(float a, float b) {
    __half2 t = __floats2half2_rn(a, b);
    return *(uint32_t*)&t;
}

// gemm smem swizzle (64B rows, 4x 16B chunks)
__device__ __forceinline__ uint32_t swz(int r, int c) {
    return (uint32_t)(r * 64 + ((c ^ ((r >> 1) & 3)) << 4));
}
// 256B rows, 16x 16B chunks
__device__ __forceinline__ uint32_t swzq(int r, int c) {
    return (uint32_t)(r * 256 + ((c ^ (r & 7)) << 4));
}
// 128B rows, 8x 16B chunks
__device__ __forceinline__ uint32_t swzv(int r, int c) {
    return (uint32_t)(r * 128 + ((c ^ (r & 7)) << 4));
}

__device__ __forceinline__ uint2 cvt4h(float4 v) {
    uint2 o;
    o.x = packh2(v.x, v.y);
    o.y = packh2(v.z, v.w);
    return o;
}

// ---------------------------------------------------------------------------
// Merged preprocessing: fp16 conversions of x/Wqkv/Wo + cache copies.
// ---------------------------------------------------------------------------
#define P_N0 (NTOK * HID_ / 4)                       // x
#define P_N1 (P_N0 + QKV_N * HID_ / 4)               // + Wqkv
#define P_N2 (P_N1 + HID_ * HID_ / 4)                // + Wo
#define P_N3 (P_N2 + NSLOTS_ * HKV_ * D_ / 4)        // + caches

__global__ void prep(const float4* __restrict__ x, const float4* __restrict__ wq,
                     const float4* __restrict__ wo,
                     const float4* __restrict__ kci, const float4* __restrict__ vci,
                     uint2* __restrict__ xf, uint2* __restrict__ wqf,
                     uint2* __restrict__ wof,
                     float4* __restrict__ kc, float4* __restrict__ vc)
{
    int i = blockIdx.x * blockDim.x + threadIdx.x;
    if (i < P_N0) {
        xf[i] = cvt4h(x[i]);
    } else if (i < P_N1) {
        int j = i - P_N0;
        wqf[j] = cvt4h(wq[j]);
    } else if (i < P_N2) {
        int j = i - P_N1;
        wof[j] = cvt4h(wo[j]);
    } else if (i < P_N3) {
        int j = i - P_N2;
        kc[j] = kci[j];
        vc[j] = vci[j];
    }
}

// ---------------------------------------------------------------------------
// Single-pass fp16 GEMM: C = A * B^T (+bias), fp32 accumulate.
// 128x128 CTA, 32x64 warp tile, 3-stage (16 KB/stage, 48 KB total).
// ---------------------------------------------------------------------------
#define F_TILE  8192
#define F_STAGE 16384
#define F_SMEM  (3 * F_STAGE)   // 48 KB

__device__ __forceinline__ void f16_stage_load(
    const __half* __restrict__ A, const __half* __restrict__ B,
    int m0, int n0, int K, int k0, uint32_t st, int tid)
{
    #pragma unroll
    for (int it = 0; it < 4; it++) {
        int idx = tid + it * 256;      // 0..1023
        int t   = idx >> 9;            // 0: A, 1: B
        int rem = idx & 511;
        int r   = rem >> 2;
        int c   = rem & 3;
        const __half* base = t ? B : A;
        int row0 = t ? n0 : m0;
        const char* src = (const char*)(base + (size_t)(row0 + r) * K + k0) + c * 16;
        CP_ASYNC16(st + (uint32_t)t * F_TILE + swz(r, c), src);
    }
}

__global__ __launch_bounds__(256)
void gemm_f16(const __half* __restrict__ A, const __half* __restrict__ B,
              const float* __restrict__ bias, float* __restrict__ C,
              int M, int N, int K)
{
    extern __shared__ char smf[];
    uint32_t sb = s2u(smf);
    int tid = threadIdx.x;
    int wid = tid >> 5, lane = tid & 31;
    int wm = wid & 3, wn = wid >> 2;
    int mbase = wm * 32, nbase = wn * 64;
    int m0 = blockIdx.y * 128, n0 = blockIdx.x * 128;

    float acc[2][8][4];
    #pragma unroll
    for (int i = 0; i < 2; i++)
        #pragma unroll
        for (int j = 0; j < 8; j++)
            #pragma unroll
            for (int q = 0; q < 4; q++) acc[i][j][q] = 0.f;

    const int nkt = K >> 5;

    f16_stage_load(A, B, m0, n0, K, 0, sb, tid);
    CP_COMMIT();
    f16_stage_load(A, B, m0, n0, K, 32, sb + F_STAGE, tid);
    CP_COMMIT();

    int lrow = lane & 15;
    int lsel = lane >> 4;

    for (int kt = 0; kt < nkt; kt++) {
        if (kt == nkt - 1) { CP_WAIT0(); } else { CP_WAIT1(); }
        __syncthreads();
        if (kt + 2 < nkt) {
            f16_stage_load(A, B, m0, n0, K, (kt + 2) << 5,
                           sb + (uint32_t)((kt + 2) % 3) * F_STAGE, tid);
            CP_COMMIT();
        }
        uint32_t sbuf = sb + (uint32_t)(kt % 3) * F_STAGE;

        #pragma unroll
        for (int ks = 0; ks < 2; ks++) {
            int kc = ks * 2;
            uint32_t ah[2][4], bh[8][2];
            #pragma unroll
            for (int f = 0; f < 2; f++) {
                int r = mbase + f * 16 + lrow;
                int c = kc + lsel;
                LDSM4(ah[f][0], ah[f][1], ah[f][2], ah[f][3], sbuf + swz(r, c));
            }
            #pragma unroll
            for (int g = 0; g < 4; g++) {
                int r = nbase + g * 16 + lrow;
                int c = kc + lsel;
                uint32_t r0, r1, r2, r3;
                LDSM4(r0, r1, r2, r3, sbuf + F_TILE + swz(r, c));
                bh[2*g][0] = r0; bh[2*g][1] = r2;
                bh[2*g+1][0] = r1; bh[2*g+1][1] = r3;
            }
            #pragma unroll
            for (int mi = 0; mi < 2; mi++)
                #pragma unroll
                for (int nj = 0; nj < 8; nj++)
                    MMAF16(acc[mi][nj], ah[mi], bh[nj]);
        }
    }

    int erow = lane >> 2;
    int ecol = (lane & 3) * 2;
    #pragma unroll
    for (int mi = 0; mi < 2; mi++) {
        #pragma unroll
        for (int nj = 0; nj < 8; nj++) {
            int col = n0 + nbase + nj * 8 + ecol;
            float b0 = bias ? bias[col]     : 0.f;
            float b1 = bias ? bias[col + 1] : 0.f;
            int r0 = m0 + mbase + mi * 16 + erow;
            *(float2*)(C + (size_t)r0 * N + col) =
                make_float2(acc[mi][nj][0] + b0, acc[mi][nj][1] + b1);
            *(float2*)(C + (size_t)(r0 + 8) * N + col) =
                make_float2(acc[mi][nj][2] + b0, acc[mi][nj][3] + b1);
        }
    }
}

// ---------------------------------------------------------------------------
// Merged RoPE kernel: blocks [0, QB) do Q rope+scale->fp16; [QB, QB+KB) do KV.
// ---------------------------------------------------------------------------
#define ROPE_QB ((NTOK * H_ * 16) / 256)     // 6144 blocks
#define ROPE_KB (B_ * HKV_ * (S_ / 64))      // 256 blocks

__global__ __launch_bounds__(256)
void ropeall(const float* __restrict__ qkv, const float* __restrict__ cosp,
             const float* __restrict__ sinp, const int* __restrict__ slot_mapping,
             float* __restrict__ kc, float* __restrict__ vc,
             __half* __restrict__ qf, __half* __restrict__ kf,
             __half* __restrict__ vf)
{
    __shared__ float vbuf[64][132];
    int tid = threadIdx.x;

    if (blockIdx.x < ROPE_QB) {
        int idx = blockIdx.x * 256 + tid;
        int t  = idx / (H_ * 16);
        int r  = idx - t * (H_ * 16);
        int h  = r >> 4, d4 = r & 15;
        int d  = d4 * 4;
        int b  = t >> 11, s = t & 2047;

        const float* rowp = qkv + (size_t)t * QKV_N + h * D_;
        float4 x1 = *(const float4*)(rowp + d);
        float4 x2 = *(const float4*)(rowp + d + 64);
        const float* cp = cosp + (size_t)t * D_;
        const float* sp = sinp + (size_t)t * D_;
        float4 c1 = *(const float4*)(cp + d),      s1 = *(const float4*)(sp + d);
        float4 c2 = *(const float4*)(cp + d + 64), s2 = *(const float4*)(sp + d + 64);

        const float qs = 0.08838834764831845f * 1.4426950408889634f;
        float4 o1, o2;
        o1.x = (x1.x * c1.x - x2.x * s1.x) * qs;
        o1.y = (x1.y * c1.y - x2.y * s1.y) * qs;
        o1.z = (x1.z * c1.z - x2.z * s1.z) * qs;
        o1.w = (x1.w * c1.w - x2.w * s1.w) * qs;
        o2.x = (x2.x * c2.x + x1.x * s2.x) * qs;
        o2.y = (x2.y * c2.y + x1.y * s2.y) * qs;
        o2.z = (x2.z * c2.z + x1.z * s2.z) * qs;
        o2.w = (x2.w * c2.w + x1.w * s2.w) * qs;

        size_t o = ((size_t)(b * H_ + h) * S_ + s) * D_;
        *(uint2*)(qf + o + d)      = cvt4h(o1);
        *(uint2*)(qf + o + d + 64) = cvt4h(o2);
        return;
    }

    int blk = blockIdx.x - ROPE_QB;
    int st64 = blk & 31;
    int kvh  = (blk >> 5) & 1;
    int b    = blk >> 6;
    int s0 = st64 * 64;

    // ---- K: rope + fp16 + fp32 cache scatter ----
    #pragma unroll
    for (int it = 0; it < 4; it++) {
        int idx = tid + it * 256;
        int r = idx >> 4, d4 = idx & 15;
        int d = d4 * 4;
        int t = b * S_ + s0 + r;
        const float* rowp = qkv + (size_t)t * QKV_N + H_*D_ + kvh * D_;
        float4 x1 = *(const float4*)(rowp + d);
        float4 x2 = *(const float4*)(rowp + d + 64);
        const float* cp = cosp + (size_t)t * D_;
        const float* sp = sinp + (size_t)t * D_;
        float4 c1 = *(const float4*)(cp + d),      s1 = *(const float4*)(sp + d);
        float4 c2 = *(const float4*)(cp + d + 64), s2 = *(const float4*)(sp + d + 64);
        float4 o1, o2;
        o1.x = x1.x * c1.x - x2.x * s1.x;
        o1.y = x1.y * c1.y - x2.y * s1.y;
        o1.z = x1.z * c1.z - x2.z * s1.z;
        o1.w = x1.w * c1.w - x2.w * s1.w;
        o2.x = x2.x * c2.x + x1.x * s2.x;
        o2.y = x2.y * c2.y + x1.y * s2.y;
        o2.z = x2.z * c2.z + x1.z * s2.z;
        o2.w = x2.w * c2.w + x1.w * s2.w;

        int slot = slot_mapping[t];
        float* kcp = kc + (size_t)slot * (HKV_*D_) + kvh * D_;
        *(float4*)(kcp + d)      = o1;
        *(float4*)(kcp + d + 64) = o2;

        size_t ko = ((size_t)(b * HKV_ + kvh) * S_ + s0 + r) * D_;
        *(uint2*)(kf + ko + d)      = cvt4h(o1);
        *(uint2*)(kf + ko + d + 64) = cvt4h(o2);
    }

    // ---- V: fp32 cache scatter + smem transpose -> fp16 [d][s] ----
    #pragma unroll
    for (int it = 0; it < 8; it++) {
        int idx = tid + it * 256;
        int r = idx >> 5, c4 = idx & 31;
        int t = b * S_ + s0 + r;
        float4 vv = *(const float4*)(qkv + (size_t)t * QKV_N
                                     + H_*D_ + HKV_*D_ + kvh * D_ + c4 * 4);
        int slot = slot_mapping[t];
        *(float4*)(vc + (size_t)slot * (HKV_*D_) + kvh * D_ + c4 * 4) = vv;
        vbuf[r][c4*4+0] = vv.x; vbuf[r][c4*4+1] = vv.y;
        vbuf[r][c4*4+2] = vv.z; vbuf[r][c4*4+3] = vv.w;
    }
    __syncthreads();

    int d = tid >> 1, half = tid & 1;
    uint32_t hw[16];
    #pragma unroll
    for (int j = 0; j < 16; j++) {
        float x0 = vbuf[half*32 + 2*j    ][d];
        float x1 = vbuf[half*32 + 2*j + 1][d];
        hw[j] = packh2(x0, x1);
    }
    size_t o = ((size_t)(b * HKV_ + kvh) * D_ + d) * S_ + s0 + half * 32;
    #pragma unroll
    for (int q = 0; q < 4; q++)
        *(uint4*)(vf + o + q * 8) = *(uint4*)&hw[q * 4];
}

// ---------------------------------------------------------------------------
// fp16 tensor-core flash attention. BLOCK_M=128 (8 warps x m16), BLOCK_N=64.
// Q 32KB resident; K+V stages 32KB x2 double-buffered. Heavy-first.
// ---------------------------------------------------------------------------
#define A3_QBYTES 32768
#define A3_STAGE  32768      // K 16KB + V 16KB
#define A3_SMEM   (A3_QBYTES + 2 * A3_STAGE)  // 98304

__global__ __launch_bounds__(256)
void attn3(const __half* __restrict__ qf, const __half* __restrict__ kf,
           const __half* __restrict__ vf, __half* __restrict__ aof)
{
    extern __shared__ char sm3[];
    uint32_t sb = s2u(sm3);
    int qt = (int)gridDim.x - 1 - (int)blockIdx.x;   // heavy-first
    int h = blockIdx.y, b = blockIdx.z;
    int kvh = h / NGROUPS_;
    int q0 = qt * 128;
    int tid = threadIdx.x, wid = tid >> 5, lane = tid & 31;
    int lrow = lane & 15, lsel = lane >> 4;

    const char* q_base = (const char*)(qf + ((size_t)(b * H_ + h) * S_ + q0) * D_);
    const char* k_base = (const char*)(kf + ((size_t)(b * HKV_ + kvh) * S_) * D_);
    const char* v_base = (const char*)(vf + ((size_t)(b * HKV_ + kvh) * D_) * S_);

    // Q tile: 128 rows x 256B
    #pragma unroll
    for (int it = 0; it < 8; it++) {
        int idx = tid + it * 256;
        int r = idx >> 4, c = idx & 15;
        CP_ASYNC16(sb + swzq(r, c), q_base + r * 256 + c * 16);
    }

    const int nt = 2 * qt + 2;

    auto load_kv = [&](int t, int st_i) {
        uint32_t st = sb + A3_QBYTES + (uint32_t)st_i * A3_STAGE;
        int k0 = t * 64;
        // K: 64 rows x 256B
        #pragma unroll
        for (int it = 0; it < 4; it++) {
            int idx = tid + it * 256;
            int r = idx >> 4, c = idx & 15;
            CP_ASYNC16(st + swzq(r, c), k_base + (size_t)(k0 + r) * 256 + c * 16);
        }
        // V: 128 rows (d) x 128B (64 seq fp16)
        #pragma unroll
        for (int it = 0; it < 4; it++) {
            int idx = tid + it * 256;
            int r = idx >> 3, c = idx & 7;
            CP_ASYNC16(st + 16384 + swzv(r, c),
                       v_base + (size_t)r * (S_ * 2) + k0 * 2 + c * 16);
        }
    };

    load_kv(0, 0);
    CP_COMMIT();

    float oacc[16][4];
    #pragma unroll
    for (int i = 0; i < 16; i++)
        #pragma unroll
        for (int j = 0; j < 4; j++) oacc[i][j] = 0.f;
    float m0 = -1e30f, m1 = -1e30f, l0 = 0.f, l1 = 0.f;

    for (int t = 0; t < nt; t++) {
        uint32_t st = sb + A3_QBYTES + (uint32_t)(t & 1) * A3_STAGE;
        if (t + 1 < nt) {
            load_kv(t + 1, (t + 1) & 1);
            CP_COMMIT();
            CP_WAIT1();
        } else {
            CP_WAIT0();
        }
        __syncthreads();

        // ---- S = Q K^T ----
        float sacc[8][4];
        #pragma unroll
        for (int i = 0; i < 8; i++)
            #pragma unroll
            for (int j = 0; j < 4; j++) sacc[i][j] = 0.f;

        #pragma unroll
        for (int kc = 0; kc < 8; kc++) {
            uint32_t qa[4];
            LDSM4(qa[0], qa[1], qa[2], qa[3],
                  sb + swzq(wid * 16 + lrow, kc * 2 + lsel));
            uint32_t bh[8][2];
            #pragma unroll
            for (int g = 0; g < 4; g++) {
                uint32_t r0, r1, r2, r3;
                LDSM4(r0, r1, r2, r3, st + swzq(g * 16 + lrow, kc * 2 + lsel));
                bh[2*g][0] = r0; bh[2*g][1] = r2;
                bh[2*g+1][0] = r1; bh[2*g+1][1] = r3;
            }
            #pragma unroll
            for (int nj = 0; nj < 8; nj++)
                MMAF16(sacc[nj], qa, bh[nj]);
        }

        // ---- causal mask (last two tiles only) ----
        int k0 = t * 64;
        if (t >= nt - 2) {
            int qr0 = q0 + wid * 16 + (lane >> 2);
            int qr1 = qr0 + 8;
            #pragma unroll
            for (int nj = 0; nj < 8; nj++) {
                int kcol = k0 + nj * 8 + (lane & 3) * 2;
                if (kcol     > qr0) sacc[nj][0] = -1e30f;
                if (kcol + 1 > qr0) sacc[nj][1] = -1e30f;
                if (kcol     > qr1) sacc[nj][2] = -1e30f;
                if (kcol + 1 > qr1) sacc[nj][3] = -1e30f;
            }
        }

        // ---- online softmax (exp2 domain, Q pre-scaled) ----
        float mx0 = -1e30f, mx1 = -1e30f;
        #pragma unroll
        for (int nj = 0; nj < 8; nj++) {
            mx0 = fmaxf(mx0, fmaxf(sacc[nj][0], sacc[nj][1]));
            mx1 = fmaxf(mx1, fmaxf(sacc[nj][2], sacc[nj][3]));
        }
        mx0 = fmaxf(mx0, __shfl_xor_sync(0xffffffffu, mx0, 1));
        mx0 = fmaxf(mx0, __shfl_xor_sync(0xffffffffu, mx0, 2));
        mx1 = fmaxf(mx1, __shfl_xor_sync(0xffffffffu, mx1, 1));
        mx1 = fmaxf(mx1, __shfl_xor_sync(0xffffffffu, mx1, 2));
        float nm0 = fmaxf(m0, mx0), nm1 = fmaxf(m1, mx1);
        float f0 = ex2f(m0 - nm0), f1 = ex2f(m1 - nm1);
        m0 = nm0; m1 = nm1;

        uint32_t ph[4][4];
        float rs0 = 0.f, rs1 = 0.f;
        #pragma unroll
        for (int j = 0; j < 4; j++) {
            float pe0 = ex2f(sacc[2*j][0] - nm0);
            float pe1 = ex2f(sacc[2*j][1] - nm0);
            float pe2 = ex2f(sacc[2*j][2] - nm1);
            float pe3 = ex2f(sacc[2*j][3] - nm1);
            float po0 = ex2f(sacc[2*j+1][0] - nm0);
            float po1 = ex2f(sacc[2*j+1][1] - nm0);
            float po2 = ex2f(sacc[2*j+1][2] - nm1);
            float po3 = ex2f(sacc[2*j+1][3] - nm1);
            rs0 += pe0 + pe1 + po0 + po1;
            rs1 += pe2 + pe3 + po2 + po3;
            ph[j][0] = packh2(pe0, pe1);
            ph[j][1] = packh2(pe2, pe3);
            ph[j][2] = packh2(po0, po1);
            ph[j][3] = packh2(po2, po3);
        }
        rs0 += __shfl_xor_sync(0xffffffffu, rs0, 1);
        rs0 += __shfl_xor_sync(0xffffffffu, rs0, 2);
        rs1 += __shfl_xor_sync(0xffffffffu, rs1, 1);
        rs1 += __shfl_xor_sync(0xffffffffu, rs1, 2);
        l0 = l0 * f0 + rs0;
        l1 = l1 * f1 + rs1;
        #pragma unroll
        for (int nj = 0; nj < 16; nj++) {
            oacc[nj][0] *= f0; oacc[nj][1] *= f0;
            oacc[nj][2] *= f1; oacc[nj][3] *= f1;
        }

        // ---- O += P V ----
        #pragma unroll
        for (int j = 0; j < 4; j++) {
            #pragma unroll
            for (int g = 0; g < 8; g++) {
                uint32_t r0, r1, r2, r3;
                LDSM4(r0, r1, r2, r3, st + 16384 + swzv(g * 16 + lrow, j * 2 + lsel));
                uint32_t vh0[2] = {r0, r2}, vh1[2] = {r1, r3};
                MMAF16(oacc[2*g],   ph[j], vh0);
                MMAF16(oacc[2*g+1], ph[j], vh1);
            }
        }
        __syncthreads();
    }

    // ---- epilogue: fp16 out ----
    float inv0 = 1.f / l0, inv1 = 1.f / l1;
    int r0g = q0 + wid * 16 + (lane >> 2);
    #pragma unroll
    for (int nj = 0; nj < 16; nj++) {
        int d = nj * 8 + (lane & 3) * 2;
        __half2 v0 = __floats2half2_rn(oacc[nj][0] * inv0, oacc[nj][1] * inv0);
        __half2 v1 = __floats2half2_rn(oacc[nj][2] * inv1, oacc[nj][3] * inv1);
        *(__half2*)(aof + ((size_t)(b * S_ + r0g)) * HID_ + h * D_ + d)     = v0;
        *(__half2*)(aof + ((size_t)(b * S_ + r0g + 8)) * HID_ + h * D_ + d) = v1;
    }
}

// ---------------------------------------------------------------------------
extern "C" void kernel_launch(void* const* d_in, const int* in_sizes, int n_in,
                              void* d_out, int out_size)
{
    const float* x     = (const float*)d_in[0];
    const float* cosp  = (const float*)d_in[1];
    const float* sinp  = (const float*)d_in[2];
    const float* kci   = (const float*)d_in[3];
    const float* vci   = (const float*)d_in[4];
    const int*   slot  = (const int*)  d_in[5];
    const float* Wqkv  = (const float*)d_in[6];
    const float* bqkv  = (const float*)d_in[7];
    const float* Wo    = (const float*)d_in[8];

    float* out = (float*)d_out;
    float* kc  = out + (size_t)NTOK * HID_;
    float* vc  = kc  + (size_t)NSLOTS_ * HKV_ * D_;

    float* qkv; cudaGetSymbolAddress((void**)&qkv, g_qkv);
    __half *xf, *wqf, *wof, *aof, *qf, *kf, *vf;
    cudaGetSymbolAddress((void**)&xf,  g_xf);
    cudaGetSymbolAddress((void**)&wqf, g_wqf);
    cudaGetSymbolAddress((void**)&wof, g_wof);
    cudaGetSymbolAddress((void**)&aof, g_aof);
    cudaGetSymbolAddress((void**)&qf,  g_qf);
    cudaGetSymbolAddress((void**)&kf,  g_kf);
    cudaGetSymbolAddress((void**)&vf,  g_vf);

    cudaFuncSetAttribute(gemm_f16, cudaFuncAttributeMaxDynamicSharedMemorySize, F_SMEM);
    cudaFuncSetAttribute(attn3, cudaFuncAttributeMaxDynamicSharedMemorySize, A3_SMEM);

    // 0) merged preprocessing: fp16 conversions + cache copies
    prep<<<(P_N3 + 255) / 256, 256>>>((const float4*)x, (const float4*)Wqkv,
                                      (const float4*)Wo, (const float4*)kci,
                                      (const float4*)vci,
                                      (uint2*)xf, (uint2*)wqf, (uint2*)wof,
                                      (float4*)kc, (float4*)vc);

    // 1) QKV projection (fp16 tensor cores, fp32 accum + bias)
    gemm_f16<<<dim3(QKV_N / 128, NTOK / 128), 256, F_SMEM>>>(
        xf, wqf, bqkv, qkv, NTOK, QKV_N, HID_);

    // 2) Merged RoPE + fp16 convert + cache scatter
    ropeall<<<ROPE_QB + ROPE_KB, 256>>>(qkv, cosp, sinp, slot,
                                        kc, vc, qf, kf, vf);

    // 3) fp16 tensor-core flash attention
    attn3<<<dim3(S_ / 128, H_, B_), 256, A3_SMEM>>>(qf, kf, vf, aof);

    // 4) Output projection (fp16 tensor cores)
    gemm_f16<<<dim3(HID_ / 128, NTOK / 128), 256, F_SMEM>>>(
        aof, wof, nullptr, out, NTOK, HID_, HID_);
}

// round 14
// speedup vs baseline: 2.7967x; 1.1231x over previous
#include <cuda_runtime.h>
#include <cuda_bf16.h>
#include <cuda_fp16.h>
#include <math.h>
#include <stdint.h>

// Problem constants
#define B_    4
#define S_    2048
#define HID_  1536
#define H_    12
#define HKV_  2
#define D_    128
#define NGROUPS_ 6
#define NSLOTS_ 16384
#define NTOK  (B_ * S_)            // 8192
#define QKV_N (H_*D_ + 2*HKV_*D_)  // 2048

// Scratch (device globals; allocation in kernel_launch is forbidden)
__device__ float  g_qkv[(size_t)NTOK * QKV_N];          // fp32 QKV (rope input)
__device__ __half g_xf [(size_t)NTOK * HID_];           // fp16 x
__device__ __half g_wqf[(size_t)QKV_N * HID_];          // fp16 Wqkv
__device__ __half g_wof[(size_t)HID_ * HID_];           // fp16 Wo
__device__ __half g_aof[(size_t)NTOK * HID_];           // fp16 attention out
__device__ __half g_qf [(size_t)B_ * H_ * S_ * D_];     // fp16 Q (scaled, roped)
__device__ __half g_kf [(size_t)B_ * HKV_ * S_ * D_];   // fp16 K (roped)
__device__ __half g_vf [(size_t)B_ * HKV_ * D_ * S_];   // fp16 V transposed [d][s]

// ---------------------------------------------------------------------------
// Portable PTX helpers
// ---------------------------------------------------------------------------
__device__ __forceinline__ uint32_t s2u(const void* p) {
    uint32_t a;
    asm("{ .reg .u64 t; cvta.to.shared.u64 t, %1; cvt.u32.u64 %0, t; }"
        : "=r"(a) : "l"(p));
    return a;
}

#define CP_ASYNC16(dst, src) \
    asm volatile("cp.async.cg.shared.global [%0], [%1], 16;" \
                 :: "r"(dst), "l"(src))
#define CP_COMMIT() asm volatile("cp.async.commit_group;")
#define CP_WAIT1()  asm volatile("cp.async.wait_group 1;")
#define CP_WAIT0()  asm volatile("cp.async.wait_group 0;")

#define LDSM4(r0, r1, r2, r3, addr) \
    asm volatile("ldmatrix.sync.aligned.m8n8.x4.shared.b16 {%0,%1,%2,%3}, [%4];" \
                 : "=r"(r0), "=r"(r1), "=r"(r2), "=r"(r3) : "r"(addr))

#define MMAF16(d, a, b) \
    asm volatile("mma.sync.aligned.m16n8k16.row.col.f32.f16.f16.f32 " \
                 "{%0,%1,%2,%3}, {%4,%5,%6,%7}, {%8,%9}, {%0,%1,%2,%3};" \
                 : "+f"((d)[0]), "+f"((d)[1]), "+f"((d)[2]), "+f"((d)[3]) \
                 : "r"((a)[0]), "r"((a)[1]), "r"((a)[2]), "r"((a)[3]), \
                   "r"((b)[0]), "r"((b)[1]))

__device__ __forceinline__ float ex2f(float x) {
    float r;
    asm("ex2.approx.ftz.f32 %0, %1;" : "=f"(r) : "f"(x));
    return r;
}

__device__ __forceinline__ uint32_t packh2(float a, float b) {
    __half2 t = __floats2half2_rn(a, b);
    return *(uint32_t*)&t;
}

// 256B rows, 16x 16B chunks
__device__ __forceinline__ uint32_t swzq(int r, int c) {
    return (uint32_t)(r * 256 + ((c ^ (r & 7)) << 4));
}
// 128B rows, 8x 16B chunks
__device__ __forceinline__ uint32_t swzv(int r, int c) {
    return (uint32_t)(r * 128 + ((c ^ (r & 7)) << 4));
}

__device__ __forceinline__ uint2 cvt4h(float4 v) {
    uint2 o;
    o.x = packh2(v.x, v.y);
    o.y = packh2(v.z, v.w);
    return o;
}

// ---------------------------------------------------------------------------
// Merged preprocessing: fp16 conversions of x/Wqkv/Wo + cache copies.
// ---------------------------------------------------------------------------
#define P_N0 (NTOK * HID_ / 4)                       // x
#define P_N1 (P_N0 + QKV_N * HID_ / 4)               // + Wqkv
#define P_N2 (P_N1 + HID_ * HID_ / 4)                // + Wo
#define P_N3 (P_N2 + NSLOTS_ * HKV_ * D_ / 4)        // + caches

__global__ void prep(const float4* __restrict__ x, const float4* __restrict__ wq,
                     const float4* __restrict__ wo,
                     const float4* __restrict__ kci, const float4* __restrict__ vci,
                     uint2* __restrict__ xf, uint2* __restrict__ wqf,
                     uint2* __restrict__ wof,
                     float4* __restrict__ kc, float4* __restrict__ vc)
{
    int i = blockIdx.x * blockDim.x + threadIdx.x;
    if (i < P_N0) {
        xf[i] = cvt4h(x[i]);
    } else if (i < P_N1) {
        int j = i - P_N0;
        wqf[j] = cvt4h(wq[j]);
    } else if (i < P_N2) {
        int j = i - P_N1;
        wof[j] = cvt4h(wo[j]);
    } else if (i < P_N3) {
        int j = i - P_N2;
        kc[j] = kci[j];
        vc[j] = vci[j];
    }
}

// ---------------------------------------------------------------------------
// Single-pass fp16 GEMM: C = A * B^T (+bias), fp32 accumulate.
// 128x128 CTA, 32x64 warp tile, K-chunk 64, 3-stage (32 KB/stage, 96 KB).
// ---------------------------------------------------------------------------
#define F_TILE  16384                   // 128 rows x 128 B
#define F_STAGE 32768
#define F_SMEM  (3 * F_STAGE)           // 96 KB

__device__ __forceinline__ void f16_stage_load(
    const __half* __restrict__ A, const __half* __restrict__ B,
    int m0, int n0, int K, int k0, uint32_t st, int tid)
{
    #pragma unroll
    for (int it = 0; it < 8; it++) {
        int idx = tid + it * 256;      // 0..2047
        int t   = idx >> 10;           // 0: A, 1: B
        int rem = idx & 1023;
        int r   = rem >> 3;            // row 0..127
        int c   = rem & 7;             // 16B chunk 0..7
        const __half* base = t ? B : A;
        int row0 = t ? n0 : m0;
        const char* src = (const char*)(base + (size_t)(row0 + r) * K + k0) + c * 16;
        CP_ASYNC16(st + (uint32_t)t * F_TILE + swzv(r, c), src);
    }
}

__global__ __launch_bounds__(256)
void gemm_f16(const __half* __restrict__ A, const __half* __restrict__ B,
              const float* __restrict__ bias, float* __restrict__ C,
              int M, int N, int K)
{
    extern __shared__ char smf[];
    uint32_t sb = s2u(smf);
    int tid = threadIdx.x;
    int wid = tid >> 5, lane = tid & 31;
    int wm = wid & 3, wn = wid >> 2;
    int mbase = wm * 32, nbase = wn * 64;
    int m0 = blockIdx.y * 128, n0 = blockIdx.x * 128;

    float acc[2][8][4];
    #pragma unroll
    for (int i = 0; i < 2; i++)
        #pragma unroll
        for (int j = 0; j < 8; j++)
            #pragma unroll
            for (int q = 0; q < 4; q++) acc[i][j][q] = 0.f;

    const int nkt = K >> 6;   // K-chunks of 64

    f16_stage_load(A, B, m0, n0, K, 0, sb, tid);
    CP_COMMIT();
    f16_stage_load(A, B, m0, n0, K, 64, sb + F_STAGE, tid);
    CP_COMMIT();

    int lrow = lane & 15;
    int lsel = lane >> 4;

    for (int kt = 0; kt < nkt; kt++) {
        if (kt == nkt - 1) { CP_WAIT0(); } else { CP_WAIT1(); }
        __syncthreads();
        if (kt + 2 < nkt) {
            f16_stage_load(A, B, m0, n0, K, (kt + 2) << 6,
                           sb + (uint32_t)((kt + 2) % 3) * F_STAGE, tid);
            CP_COMMIT();
        }
        uint32_t sbuf = sb + (uint32_t)(kt % 3) * F_STAGE;

        #pragma unroll
        for (int ks = 0; ks < 4; ks++) {
            int kc = ks * 2 + lsel;
            uint32_t ah[2][4];
            #pragma unroll
            for (int f = 0; f < 2; f++) {
                int r = mbase + f * 16 + lrow;
                LDSM4(ah[f][0], ah[f][1], ah[f][2], ah[f][3], sbuf + swzv(r, kc));
            }
            #pragma unroll
            for (int g = 0; g < 4; g++) {
                int r = nbase + g * 16 + lrow;
                uint32_t r0, r1, r2, r3;
                LDSM4(r0, r1, r2, r3, sbuf + F_TILE + swzv(r, kc));
                uint32_t b0[2] = {r0, r2}, b1[2] = {r1, r3};
                #pragma unroll
                for (int mi = 0; mi < 2; mi++) {
                    MMAF16(acc[mi][2*g],   ah[mi], b0);
                    MMAF16(acc[mi][2*g+1], ah[mi], b1);
                }
            }
        }
    }

    int erow = lane >> 2;
    int ecol = (lane & 3) * 2;
    #pragma unroll
    for (int mi = 0; mi < 2; mi++) {
        #pragma unroll
        for (int nj = 0; nj < 8; nj++) {
            int col = n0 + nbase + nj * 8 + ecol;
            float b0 = bias ? bias[col]     : 0.f;
            float b1 = bias ? bias[col + 1] : 0.f;
            int r0 = m0 + mbase + mi * 16 + erow;
            *(float2*)(C + (size_t)r0 * N + col) =
                make_float2(acc[mi][nj][0] + b0, acc[mi][nj][1] + b1);
            *(float2*)(C + (size_t)(r0 + 8) * N + col) =
                make_float2(acc[mi][nj][2] + b0, acc[mi][nj][3] + b1);
        }
    }
}

// ---------------------------------------------------------------------------
// Merged RoPE kernel: blocks [0, QB) do Q rope+scale->fp16; [QB, QB+KB) do KV.
// ---------------------------------------------------------------------------
#define ROPE_QB ((NTOK * H_ * 16) / 256)     // 6144 blocks
#define ROPE_KB (B_ * HKV_ * (S_ / 64))      // 256 blocks

__global__ __launch_bounds__(256)
void ropeall(const float* __restrict__ qkv, const float* __restrict__ cosp,
             const float* __restrict__ sinp, const int* __restrict__ slot_mapping,
             float* __restrict__ kc, float* __restrict__ vc,
             __half* __restrict__ qf, __half* __restrict__ kf,
             __half* __restrict__ vf)
{
    __shared__ float vbuf[64][132];
    int tid = threadIdx.x;

    if (blockIdx.x < ROPE_QB) {
        int idx = blockIdx.x * 256 + tid;
        int t  = idx / (H_ * 16);
        int r  = idx - t * (H_ * 16);
        int h  = r >> 4, d4 = r & 15;
        int d  = d4 * 4;
        int b  = t >> 11, s = t & 2047;

        const float* rowp = qkv + (size_t)t * QKV_N + h * D_;
        float4 x1 = *(const float4*)(rowp + d);
        float4 x2 = *(const float4*)(rowp + d + 64);
        const float* cp = cosp + (size_t)t * D_;
        const float* sp = sinp + (size_t)t * D_;
        float4 c1 = *(const float4*)(cp + d),      s1 = *(const float4*)(sp + d);
        float4 c2 = *(const float4*)(cp + d + 64), s2 = *(const float4*)(sp + d + 64);

        const float qs = 0.08838834764831845f * 1.4426950408889634f;
        float4 o1, o2;
        o1.x = (x1.x * c1.x - x2.x * s1.x) * qs;
        o1.y = (x1.y * c1.y - x2.y * s1.y) * qs;
        o1.z = (x1.z * c1.z - x2.z * s1.z) * qs;
        o1.w = (x1.w * c1.w - x2.w * s1.w) * qs;
        o2.x = (x2.x * c2.x + x1.x * s2.x) * qs;
        o2.y = (x2.y * c2.y + x1.y * s2.y) * qs;
        o2.z = (x2.z * c2.z + x1.z * s2.z) * qs;
        o2.w = (x2.w * c2.w + x1.w * s2.w) * qs;

        size_t o = ((size_t)(b * H_ + h) * S_ + s) * D_;
        *(uint2*)(qf + o + d)      = cvt4h(o1);
        *(uint2*)(qf + o + d + 64) = cvt4h(o2);
        return;
    }

    int blk = blockIdx.x - ROPE_QB;
    int st64 = blk & 31;
    int kvh  = (blk >> 5) & 1;
    int b    = blk >> 6;
    int s0 = st64 * 64;

    // ---- K: rope + fp16 + fp32 cache scatter ----
    #pragma unroll
    for (int it = 0; it < 4; it++) {
        int idx = tid + it * 256;
        int r = idx >> 4, d4 = idx & 15;
        int d = d4 * 4;
        int t = b * S_ + s0 + r;
        const float* rowp = qkv + (size_t)t * QKV_N + H_*D_ + kvh * D_;
        float4 x1 = *(const float4*)(rowp + d);
        float4 x2 = *(const float4*)(rowp + d + 64);
        const float* cp = cosp + (size_t)t * D_;
        const float* sp = sinp + (size_t)t * D_;
        float4 c1 = *(const float4*)(cp + d),      s1 = *(const float4*)(sp + d);
        float4 c2 = *(const float4*)(cp + d + 64), s2 = *(const float4*)(sp + d + 64);
        float4 o1, o2;
        o1.x = x1.x * c1.x - x2.x * s1.x;
        o1.y = x1.y * c1.y - x2.y * s1.y;
        o1.z = x1.z * c1.z - x2.z * s1.z;
        o1.w = x1.w * c1.w - x2.w * s1.w;
        o2.x = x2.x * c2.x + x1.x * s2.x;
        o2.y = x2.y * c2.y + x1.y * s2.y;
        o2.z = x2.z * c2.z + x1.z * s2.z;
        o2.w = x2.w * c2.w + x1.w * s2.w;

        int slot = slot_mapping[t];
        float* kcp = kc + (size_t)slot * (HKV_*D_) + kvh * D_;
        *(float4*)(kcp + d)      = o1;
        *(float4*)(kcp + d + 64) = o2;

        size_t ko = ((size_t)(b * HKV_ + kvh) * S_ + s0 + r) * D_;
        *(uint2*)(kf + ko + d)      = cvt4h(o1);
        *(uint2*)(kf + ko + d + 64) = cvt4h(o2);
    }

    // ---- V: fp32 cache scatter + smem transpose -> fp16 [d][s] ----
    #pragma unroll
    for (int it = 0; it < 8; it++) {
        int idx = tid + it * 256;
        int r = idx >> 5, c4 = idx & 31;
        int t = b * S_ + s0 + r;
        float4 vv = *(const float4*)(qkv + (size_t)t * QKV_N
                                     + H_*D_ + HKV_*D_ + kvh * D_ + c4 * 4);
        int slot = slot_mapping[t];
        *(float4*)(vc + (size_t)slot * (HKV_*D_) + kvh * D_ + c4 * 4) = vv;
        vbuf[r][c4*4+0] = vv.x; vbuf[r][c4*4+1] = vv.y;
        vbuf[r][c4*4+2] = vv.z; vbuf[r][c4*4+3] = vv.w;
    }
    __syncthreads();

    int d = tid >> 1, half = tid & 1;
    uint32_t hw[16];
    #pragma unroll
    for (int j = 0; j < 16; j++) {
        float x0 = vbuf[half*32 + 2*j    ][d];
        float x1 = vbuf[half*32 + 2*j + 1][d];
        hw[j] = packh2(x0, x1);
    }
    size_t o = ((size_t)(b * HKV_ + kvh) * D_ + d) * S_ + s0 + half * 32;
    #pragma unroll
    for (int q = 0; q < 4; q++)
        *(uint4*)(vf + o + q * 8) = *(uint4*)&hw[q * 4];
}

// ---------------------------------------------------------------------------
// fp16 tensor-core flash attention. BLOCK_M=128 (8 warps x m16), BLOCK_N=128.
// Q 32KB resident; K 32KB + V 32KB per stage, double-buffered (160 KB total).
// Heavy-first scheduling; fp16 output.
// ---------------------------------------------------------------------------
#define A4_QBYTES 32768
#define A4_STAGE  65536
#define A4_SMEM   (A4_QBYTES + 2 * A4_STAGE)  // 163840

__global__ __launch_bounds__(256)
void attn4(const __half* __restrict__ qf, const __half* __restrict__ kf,
           const __half* __restrict__ vf, __half* __restrict__ aof)
{
    extern __shared__ char sm4[];
    uint32_t sb = s2u(sm4);
    int qt = (int)gridDim.x - 1 - (int)blockIdx.x;   // heavy-first
    int h = blockIdx.y, b = blockIdx.z;
    int kvh = h / NGROUPS_;
    int q0 = qt * 128;
    int tid = threadIdx.x, wid = tid >> 5, lane = tid & 31;
    int lrow = lane & 15, lsel = lane >> 4;

    const char* q_base = (const char*)(qf + ((size_t)(b * H_ + h) * S_ + q0) * D_);
    const char* k_base = (const char*)(kf + ((size_t)(b * HKV_ + kvh) * S_) * D_);
    const char* v_base = (const char*)(vf + ((size_t)(b * HKV_ + kvh) * D_) * S_);

    // Q tile: 128 rows x 256B
    #pragma unroll
    for (int it = 0; it < 8; it++) {
        int idx = tid + it * 256;
        int r = idx >> 4, c = idx & 15;
        CP_ASYNC16(sb + swzq(r, c), q_base + r * 256 + c * 16);
    }

    const int nt = qt + 1;   // 128-wide KV tiles

    auto load_kv = [&](int t, int st_i) {
        uint32_t st = sb + A4_QBYTES + (uint32_t)st_i * A4_STAGE;
        int k0 = t * 128;
        // K: 128 rows x 256B
        #pragma unroll
        for (int it = 0; it < 8; it++) {
            int idx = tid + it * 256;
            int r = idx >> 4, c = idx & 15;
            CP_ASYNC16(st + swzq(r, c), k_base + (size_t)(k0 + r) * 256 + c * 16);
        }
        // V: 128 d-rows x 256B (128 seq fp16)
        #pragma unroll
        for (int it = 0; it < 8; it++) {
            int idx = tid + it * 256;
            int r = idx >> 4, c = idx & 15;
            CP_ASYNC16(st + 32768 + swzq(r, c),
                       v_base + (size_t)r * (S_ * 2) + k0 * 2 + c * 16);
        }
    };

    load_kv(0, 0);
    CP_COMMIT();

    float oacc[16][4];
    #pragma unroll
    for (int i = 0; i < 16; i++)
        #pragma unroll
        for (int j = 0; j < 4; j++) oacc[i][j] = 0.f;
    float m0 = -1e30f, m1 = -1e30f, l0 = 0.f, l1 = 0.f;

    for (int t = 0; t < nt; t++) {
        uint32_t st = sb + A4_QBYTES + (uint32_t)(t & 1) * A4_STAGE;
        if (t + 1 < nt) {
            load_kv(t + 1, (t + 1) & 1);
            CP_COMMIT();
            CP_WAIT1();
        } else {
            CP_WAIT0();
        }
        __syncthreads();

        // ---- S = Q K^T (128 cols) ----
        float sacc[16][4];
        #pragma unroll
        for (int i = 0; i < 16; i++)
            #pragma unroll
            for (int j = 0; j < 4; j++) sacc[i][j] = 0.f;

        #pragma unroll
        for (int kc = 0; kc < 8; kc++) {
            uint32_t qa[4];
            LDSM4(qa[0], qa[1], qa[2], qa[3],
                  sb + swzq(wid * 16 + lrow, kc * 2 + lsel));
            #pragma unroll
            for (int g = 0; g < 8; g++) {
                uint32_t r0, r1, r2, r3;
                LDSM4(r0, r1, r2, r3, st + swzq(g * 16 + lrow, kc * 2 + lsel));
                uint32_t b0[2] = {r0, r2}, b1[2] = {r1, r3};
                MMAF16(sacc[2*g],   qa, b0);
                MMAF16(sacc[2*g+1], qa, b1);
            }
        }

        // ---- causal mask (last tile only) ----
        int k0 = t * 128;
        if (t == nt - 1) {
            int qr0 = q0 + wid * 16 + (lane >> 2);
            int qr1 = qr0 + 8;
            #pragma unroll
            for (int nj = 0; nj < 16; nj++) {
                int kcol = k0 + nj * 8 + (lane & 3) * 2;
                if (kcol     > qr0) sacc[nj][0] = -1e30f;
                if (kcol + 1 > qr0) sacc[nj][1] = -1e30f;
                if (kcol     > qr1) sacc[nj][2] = -1e30f;
                if (kcol + 1 > qr1) sacc[nj][3] = -1e30f;
            }
        }

        // ---- online softmax (exp2 domain, Q pre-scaled) ----
        float mx0 = -1e30f, mx1 = -1e30f;
        #pragma unroll
        for (int nj = 0; nj < 16; nj++) {
            mx0 = fmaxf(mx0, fmaxf(sacc[nj][0], sacc[nj][1]));
            mx1 = fmaxf(mx1, fmaxf(sacc[nj][2], sacc[nj][3]));
        }
        mx0 = fmaxf(mx0, __shfl_xor_sync(0xffffffffu, mx0, 1));
        mx0 = fmaxf(mx0, __shfl_xor_sync(0xffffffffu, mx0, 2));
        mx1 = fmaxf(mx1, __shfl_xor_sync(0xffffffffu, mx1, 1));
        mx1 = fmaxf(mx1, __shfl_xor_sync(0xffffffffu, mx1, 2));
        float nm0 = fmaxf(m0, mx0), nm1 = fmaxf(m1, mx1);
        float f0 = ex2f(m0 - nm0), f1 = ex2f(m1 - nm1);
        m0 = nm0; m1 = nm1;

        uint32_t ph[8][4];
        float rs0 = 0.f, rs1 = 0.f;
        #pragma unroll
        for (int j = 0; j < 8; j++) {
            float pe0 = ex2f(sacc[2*j][0] - nm0);
            float pe1 = ex2f(sacc[2*j][1] - nm0);
            float pe2 = ex2f(sacc[2*j][2] - nm1);
            float pe3 = ex2f(sacc[2*j][3] - nm1);
            float po0 = ex2f(sacc[2*j+1][0] - nm0);
            float po1 = ex2f(sacc[2*j+1][1] - nm0);
            float po2 = ex2f(sacc[2*j+1][2] - nm1);
            float po3 = ex2f(sacc[2*j+1][3] - nm1);
            rs0 += pe0 + pe1 + po0 + po1;
            rs1 += pe2 + pe3 + po2 + po3;
            ph[j][0] = packh2(pe0, pe1);
            ph[j][1] = packh2(pe2, pe3);
            ph[j][2] = packh2(po0, po1);
            ph[j][3] = packh2(po2, po3);
        }
        rs0 += __shfl_xor_sync(0xffffffffu, rs0, 1);
        rs0 += __shfl_xor_sync(0xffffffffu, rs0, 2);
        rs1 += __shfl_xor_sync(0xffffffffu, rs1, 1);
        rs1 += __shfl_xor_sync(0xffffffffu, rs1, 2);
        l0 = l0 * f0 + rs0;
        l1 = l1 * f1 + rs1;
        #pragma unroll
        for (int nj = 0; nj < 16; nj++) {
            oacc[nj][0] *= f0; oacc[nj][1] *= f0;
            oacc[nj][2] *= f1; oacc[nj][3] *= f1;
        }

        // ---- O += P V ----
        #pragma unroll
        for (int j = 0; j < 8; j++) {
            #pragma unroll
            for (int g = 0; g < 8; g++) {
                uint32_t r0, r1, r2, r3;
                LDSM4(r0, r1, r2, r3, st + 32768 + swzq(g * 16 + lrow, j * 2 + lsel));
                uint32_t vh0[2] = {r0, r2}, vh1[2] = {r1, r3};
                MMAF16(oacc[2*g],   ph[j], vh0);
                MMAF16(oacc[2*g+1], ph[j], vh1);
            }
        }
        __syncthreads();
    }

    // ---- epilogue: fp16 out ----
    float inv0 = 1.f / l0, inv1 = 1.f / l1;
    int r0g = q0 + wid * 16 + (lane >> 2);
    #pragma unroll
    for (int nj = 0; nj < 16; nj++) {
        int d = nj * 8 + (lane & 3) * 2;
        __half2 v0 = __floats2half2_rn(oacc[nj][0] * inv0, oacc[nj][1] * inv0);
        __half2 v1 = __floats2half2_rn(oacc[nj][2] * inv1, oacc[nj][3] * inv1);
        *(__half2*)(aof + ((size_t)(b * S_ + r0g)) * HID_ + h * D_ + d)     = v0;
        *(__half2*)(aof + ((size_t)(b * S_ + r0g + 8)) * HID_ + h * D_ + d) = v1;
    }
}

// ---------------------------------------------------------------------------
extern "C" void kernel_launch(void* const* d_in, const int* in_sizes, int n_in,
                              void* d_out, int out_size)
{
    const float* x     = (const float*)d_in[0];
    const float* cosp  = (const float*)d_in[1];
    const float* sinp  = (const float*)d_in[2];
    const float* kci   = (const float*)d_in[3];
    const float* vci   = (const float*)d_in[4];
    const int*   slot  = (const int*)  d_in[5];
    const float* Wqkv  = (const float*)d_in[6];
    const float* bqkv  = (const float*)d_in[7];
    const float* Wo    = (const float*)d_in[8];

    float* out = (float*)d_out;
    float* kc  = out + (size_t)NTOK * HID_;
    float* vc  = kc  + (size_t)NSLOTS_ * HKV_ * D_;

    float* qkv; cudaGetSymbolAddress((void**)&qkv, g_qkv);
    __half *xf, *wqf, *wof, *aof, *qf, *kf, *vf;
    cudaGetSymbolAddress((void**)&xf,  g_xf);
    cudaGetSymbolAddress((void**)&wqf, g_wqf);
    cudaGetSymbolAddress((void**)&wof, g_wof);
    cudaGetSymbolAddress((void**)&aof, g_aof);
    cudaGetSymbolAddress((void**)&qf,  g_qf);
    cudaGetSymbolAddress((void**)&kf,  g_kf);
    cudaGetSymbolAddress((void**)&vf,  g_vf);

    cudaFuncSetAttribute(gemm_f16, cudaFuncAttributeMaxDynamicSharedMemorySize, F_SMEM);
    cudaFuncSetAttribute(attn4, cudaFuncAttributeMaxDynamicSharedMemorySize, A4_SMEM);

    // 0) merged preprocessing: fp16 conversions + cache copies
    prep<<<(P_N3 + 255) / 256, 256>>>((const float4*)x, (const float4*)Wqkv,
                                      (const float4*)Wo, (const float4*)kci,
                                      (const float4*)vci,
                                      (uint2*)xf, (uint2*)wqf, (uint2*)wof,
                                      (float4*)kc, (float4*)vc);

    // 1) QKV projection (fp16 tensor cores, fp32 accum + bias)
    gemm_f16<<<dim3(QKV_N / 128, NTOK / 128), 256, F_SMEM>>>(
        xf, wqf, bqkv, qkv, NTOK, QKV_N, HID_);

    // 2) Merged RoPE + fp16 convert + cache scatter
    ropeall<<<ROPE_QB + ROPE_KB, 256>>>(qkv, cosp, sinp, slot,
                                        kc, vc, qf, kf, vf);

    // 3) fp16 tensor-core flash attention (BLOCK_N=128)
    attn4<<<dim3(S_ / 128, H_, B_), 256, A4_SMEM>>>(qf, kf, vf, aof);

    // 4) Output projection (fp16 tensor cores)
    gemm_f16<<<dim3(HID_ / 128, NTOK / 128), 256, F_SMEM>>>(
        aof, wof, nullptr, out, NTOK, HID_, HID_);
}